// round 13
// baseline (speedup 1.0000x reference)
#include <cuda_runtime.h>
#include <cuda_fp16.h>
#include <stdint.h>
#include <stddef.h>

#define B_ 8
#define S_ 2048
#define M_ 256
#define D_ 512
#define P_ 512
#define H_ 8
#define SCALE 0.04419417382415922f   // 1/sqrt(512)

// ---------------- scratch (device globals) ----------------------------------
__device__ __half g_in_h[B_ * S_ * D_];
__device__ __half g_mem_h[B_ * M_ * D_];
__device__ __half g_ik_h[B_ * S_ * P_];
__device__ __half g_ivT_h[B_ * P_ * S_];        // transposed V
__device__ float  g_mk[B_ * M_ * P_];
__device__ float  g_mv[B_ * M_ * P_];
__device__ __half g_q_h[B_ * H_ * M_ * P_];     // [b,h,m,p]
__device__ __half g_scores_h[(size_t)B_ * H_ * M_ * S_];
__device__ __half g_probs_h[(size_t)B_ * H_ * M_ * S_];
__device__ float  g_self[B_ * H_ * M_];
__device__ __half g_concat_h[B_ * M_ * H_ * P_];
__device__ float  g_part[4 * 2048 * 512];       // split-K partials
__device__ __half g_WkT[P_ * D_];
__device__ __half g_WvT[P_ * D_];
__device__ __half g_WqT[H_ * P_ * D_];
__device__ __half g_WoT[P_ * H_ * P_];

// ---------------- low-level helpers -----------------------------------------
__device__ __forceinline__ void cpa16(uint32_t s, const void* g) {
    asm volatile("cp.async.cg.shared.global [%0], [%1], 16;\n" ::"r"(s), "l"(g));
}
#define CPA_COMMIT() asm volatile("cp.async.commit_group;\n" ::: "memory")
#define CPA_WAIT1()  asm volatile("cp.async.wait_group 1;\n" ::: "memory")

__device__ __forceinline__ void ldsm4(uint32_t* r, uint32_t addr) {
    asm volatile("ldmatrix.sync.aligned.m8n8.x4.shared.b16 {%0,%1,%2,%3}, [%4];"
        : "=r"(r[0]), "=r"(r[1]), "=r"(r[2]), "=r"(r[3]) : "r"(addr));
}
__device__ __forceinline__ void mma16816(float* d, const uint32_t* a,
                                         uint32_t b0, uint32_t b1) {
    asm volatile(
        "mma.sync.aligned.m16n8k16.row.col.f32.f16.f16.f32 "
        "{%0,%1,%2,%3},{%4,%5,%6,%7},{%8,%9},{%0,%1,%2,%3};"
        : "+f"(d[0]), "+f"(d[1]), "+f"(d[2]), "+f"(d[3])
        : "r"(a[0]), "r"(a[1]), "r"(a[2]), "r"(a[3]), "r"(b0), "r"(b1));
}

// SMEM: BK=64, rows padded to 72 halfs.
#define ROWP 72
#define STAGE_B (128 * ROWP * 2)
#define GEMM_SMEM (6 * STAGE_B)     // 110592 bytes

// ---------------- fused prep: tohalf(input,mem) + transposes -----------------
__device__ __forceinline__ void transpose_flat(const float* in, __half* out,
                                               int K, int N, int bx, int by,
                                               int tid) {
    __shared__ float t[32][33];
    int k0 = by * 32, n0 = bx * 32;
    int x = tid & 31, y = tid >> 5;   // 32 x 8
#pragma unroll
    for (int i = 0; i < 32; i += 8)
        t[y + i][x] = in[(size_t)(k0 + y + i) * N + n0 + x];
    __syncthreads();
#pragma unroll
    for (int i = 0; i < 32; i += 8)
        out[(size_t)(n0 + y + i) * K + k0 + x] = __float2half(t[x][y + i]);
}
__global__ __launch_bounds__(256) void k_prep(
    const float* __restrict__ input_seq, const float* __restrict__ mem,
    const float* __restrict__ Wk, const float* __restrict__ Wv,
    const float* __restrict__ Wq, const float* __restrict__ Wo,
    __half* __restrict__ in_h, __half* __restrict__ mem_h,
    __half* __restrict__ WkT, __half* __restrict__ WvT,
    __half* __restrict__ WqT, __half* __restrict__ WoT)
{
    int bid = blockIdx.x, tid = threadIdx.x;
    if (bid < 8192) {                 // tohalf input_seq
        size_t i = ((size_t)bid * 256 + tid) * 4;
        float4 v = *(const float4*)(input_seq + i);
        *(__half2*)(in_h + i)     = __floats2half2_rn(v.x, v.y);
        *(__half2*)(in_h + i + 2) = __floats2half2_rn(v.z, v.w);
    } else if (bid < 9216) {          // tohalf memory_cells
        size_t i = ((size_t)(bid - 8192) * 256 + tid) * 4;
        float4 v = *(const float4*)(mem + i);
        *(__half2*)(mem_h + i)     = __floats2half2_rn(v.x, v.y);
        *(__half2*)(mem_h + i + 2) = __floats2half2_rn(v.z, v.w);
    } else if (bid < 11776) {         // kvq transposes: 16x16x10
        int t2 = bid - 9216;
        int z = t2 >> 8, rem = t2 & 255;
        int bx = rem & 15, by = rem >> 4;
        const float* in; __half* out;
        if (z == 0)      { in = Wk; out = WkT; }
        else if (z == 1) { in = Wv; out = WvT; }
        else             { in = Wq + (size_t)(z - 2) * D_ * P_;
                           out = WqT + (size_t)(z - 2) * P_ * D_; }
        transpose_flat(in, out, D_, P_, bx, by, tid);
    } else {                          // Wo transpose: 16 x 128
        int t2 = bid - 11776;
        int bx = t2 & 15, by = t2 >> 4;
        transpose_flat(Wo, WoT, H_ * P_, P_, bx, by, tid);
    }
}

// ---------------- fp16 NT GEMM: 128x128 CTA tile, BK=64, 3-stage ------------
// 128 threads, 4 warps (2m x 2n), 64m x 64n per warp. Fragments via ldmatrix.
// MODE 6: combined projections. by<160: mem-side (zz: 0->mk f32, 1->mv f32,
//         2..9->q_h scatter); by>=160: input-side (zz: 0->ik_h, 1->ivT_h staged).
// MODE 2: scores -> scores_h fp16 *SCALE (smem-staged)
// MODE 3: val -> concat_h, +self*mv (smem-staged)
// MODE 5: outproj partial -> part[z] f32
template <int MODE, int K>
__global__ __launch_bounds__(128, 2) void gemm_h(
    const __half* __restrict__ A0, const __half* __restrict__ A1,
    const __half* __restrict__ B0, const __half* __restrict__ B1,
    const __half* __restrict__ B2,
    const float* __restrict__ bias0, const float* __restrict__ bias1,
    const float* __restrict__ bias2,
    float* __restrict__ F0, float* __restrict__ F1,
    __half* __restrict__ H0, __half* __restrict__ H1, __half* __restrict__ H2,
    const float* __restrict__ selfw, const float* __restrict__ mvp)
{
    extern __shared__ __align__(16) char smem[];
    const uint32_t sbase = (uint32_t)__cvta_generic_to_shared(smem);
    const uint32_t sB0 = sbase + 3 * STAGE_B;

    const int tid = threadIdx.x;
    const int lane = tid & 31, wid = tid >> 5;
    const int g = lane >> 2, tg = lane & 3;
    const int wm = wid & 1, wn = wid >> 1;       // 2m x 2n warps, 64x64 tiles
    const int n0 = blockIdx.x * 128;
    const int z = blockIdx.z;
    const int lrow = (lane & 7) + ((lane >> 3) & 1) * 8;
    const int lkb = (lane >> 4) * 8;
    const int bn_local = (lane & 7) + ((lane >> 4) & 1) * 8;
    const int bk_half = ((lane >> 3) & 1) * 8;

    int m0, part = 0, zz = 0;
    if (MODE == 6) {
        int by = blockIdx.y;
        if (by < 160) { part = 0; zz = by >> 4; m0 = (by & 15) * 128; }
        else { int t = by - 160; part = 1; zz = t >> 7; m0 = (t & 127) * 128; }
    } else {
        m0 = blockIdx.y * 128;
    }

    const __half *Ag, *Bg;
    int lda, ldb;
    if (MODE == 6) {
        lda = D_; ldb = D_;
        const __half* Bb;
        if (part == 0) {
            Ag = A0 + (size_t)m0 * lda;
            Bb = (zz == 0) ? B0 : (zz == 1) ? B1 : (B2 + (size_t)(zz - 2) * P_ * D_);
        } else {
            Ag = A1 + (size_t)m0 * lda;
            Bb = (zz == 0) ? B0 : B1;
        }
        Bg = Bb + (size_t)n0 * ldb;
    } else if (MODE == 2) {
        lda = P_; ldb = P_;
        Ag = A0 + (size_t)z * M_ * P_ + (size_t)m0 * lda;
        Bg = B0 + (size_t)(z >> 3) * S_ * P_ + (size_t)n0 * ldb;
    } else if (MODE == 3) {
        lda = S_; ldb = S_;
        Ag = A0 + (size_t)z * M_ * S_ + (size_t)m0 * lda;
        Bg = B0 + (size_t)(z >> 3) * P_ * S_ + (size_t)n0 * ldb;
    } else {  // MODE 5
        lda = H_ * P_; ldb = H_ * P_;
        Ag = A0 + (size_t)m0 * lda + z * 1024;
        Bg = B0 + (size_t)n0 * ldb + z * 1024;
    }

    // fill: 128 threads; each thread 1 row (128 rows) x 64 halfs per operand
    const __half* gA0 = Ag + (size_t)tid * lda;
    const __half* gB0 = Bg + (size_t)tid * ldb;
    const uint32_t dA0 = sbase + tid * (ROWP * 2);
    const uint32_t dB0 = sB0 + tid * (ROWP * 2);

#define FILL(j) do { \
        int _s = (j) % 3; \
        const __half* _ga = gA0 + (j) * 64; \
        const __half* _gb = gB0 + (j) * 64; \
        uint32_t _da = dA0 + _s * STAGE_B; \
        uint32_t _db = dB0 + _s * STAGE_B; \
        cpa16(_da, _ga);            cpa16(_da + 16, _ga + 8); \
        cpa16(_da + 32, _ga + 16);  cpa16(_da + 48, _ga + 24); \
        cpa16(_da + 64, _ga + 32);  cpa16(_da + 80, _ga + 40); \
        cpa16(_da + 96, _ga + 48);  cpa16(_da + 112, _ga + 56); \
        cpa16(_db, _gb);            cpa16(_db + 16, _gb + 8); \
        cpa16(_db + 32, _gb + 16);  cpa16(_db + 48, _gb + 24); \
        cpa16(_db + 64, _gb + 32);  cpa16(_db + 80, _gb + 40); \
        cpa16(_db + 96, _gb + 48);  cpa16(_db + 112, _gb + 56); \
    } while (0)

    float acc[4][8][4] = {};
    constexpr int NK = K / 64;
    FILL(0); CPA_COMMIT();
    if (NK > 1) { FILL(1); } CPA_COMMIT();
    for (int i = 0; i < NK; i++) {
        CPA_WAIT1();
        __syncthreads();
        if (i + 2 < NK) FILL(i + 2);
        CPA_COMMIT();
        const int s = i % 3;
        const uint32_t aS = sbase + s * STAGE_B;
        const uint32_t bS = sB0 + s * STAGE_B;
#pragma unroll
        for (int kk = 0; kk < 4; kk++) {
            uint32_t a[4][4];
#pragma unroll
            for (int mt = 0; mt < 4; mt++)
                ldsm4(a[mt], aS +
                    ((wm * 64 + mt * 16 + lrow) * ROWP + kk * 16 + lkb) * 2);
#pragma unroll
            for (int np = 0; np < 4; np++) {
                uint32_t br[4];
                ldsm4(br, bS +
                    ((wn * 64 + np * 16 + bn_local) * ROWP + kk * 16 + bk_half) * 2);
#pragma unroll
                for (int mt = 0; mt < 4; mt++) {
                    mma16816(acc[mt][2 * np],     a[mt], br[0], br[1]);
                    mma16816(acc[mt][2 * np + 1], a[mt], br[2], br[3]);
                }
            }
        }
    }
#undef FILL

    // ---- ivT path: SMEM-staged transpose, coalesced stores ----
    if (MODE == 6 && part == 1 && zz == 1) {
        __syncthreads();
        __half* tb = (__half*)smem;           // [128 p][136 s-pad]
#pragma unroll
        for (int mt = 0; mt < 4; mt++)
#pragma unroll
            for (int nt = 0; nt < 8; nt++) {
                int p_l = wn * 64 + nt * 8 + 2 * tg;
                float2 bi = *(const float2*)(bias1 + n0 + p_l);
#pragma unroll
                for (int rr = 0; rr < 2; rr++) {
                    int s_l = wm * 64 + mt * 16 + g + rr * 8;
                    tb[(p_l)     * 136 + s_l] = __float2half(acc[mt][nt][2 * rr] + bi.x);
                    tb[(p_l + 1) * 136 + s_l] = __float2half(acc[mt][nt][2 * rr + 1] + bi.y);
                }
            }
        __syncthreads();
        int b = m0 >> 11, s0 = m0 & 2047;
#pragma unroll
        for (int i = 0; i < 16; i++) {
            int c = i * 128 + tid;
            int p = c >> 4, off = (c & 15) * 8;
            *(float4*)&H2[((size_t)b * P_ + n0 + p) * S_ + s0 + off] =
                *(float4*)&tb[p * 136 + off];
        }
        return;
    }

    // ---- scores path: SMEM-staged, coalesced stores ----
    if (MODE == 2) {
        __syncthreads();
        __half* tb = (__half*)smem;           // [128 m][136 s-pad]
#pragma unroll
        for (int mt = 0; mt < 4; mt++)
#pragma unroll
            for (int nt = 0; nt < 8; nt++) {
                int c_l = wn * 64 + nt * 8 + 2 * tg;
#pragma unroll
                for (int rr = 0; rr < 2; rr++) {
                    int r_l = wm * 64 + mt * 16 + g + rr * 8;
                    *(__half2*)&tb[r_l * 136 + c_l] =
                        __floats2half2_rn(acc[mt][nt][2 * rr] * SCALE,
                                          acc[mt][nt][2 * rr + 1] * SCALE);
                }
            }
        __syncthreads();
#pragma unroll
        for (int i = 0; i < 16; i++) {
            int c = i * 128 + tid;
            int r = c >> 4, off = (c & 15) * 8;
            *(float4*)&H0[((size_t)z * M_ + m0 + r) * S_ + n0 + off] =
                *(float4*)&tb[r * 136 + off];
        }
        return;
    }

    // ---- val path: SMEM-staged (+self*mv), coalesced stores ----
    if (MODE == 3) {
        __syncthreads();
        __half* tb = (__half*)smem;           // [128 m][136 p-pad]
        int b = z >> 3, h = z & 7;
#pragma unroll
        for (int mt = 0; mt < 4; mt++)
#pragma unroll
            for (int nt = 0; nt < 8; nt++) {
                int c_l = wn * 64 + nt * 8 + 2 * tg;
#pragma unroll
                for (int rr = 0; rr < 2; rr++) {
                    int r_l = wm * 64 + mt * 16 + g + rr * 8;
                    int R = m0 + r_l;
                    float sw = selfw[(size_t)z * M_ + R];
                    float2 mvv = *(const float2*)(mvp +
                        ((size_t)(b * M_ + R)) * P_ + n0 + c_l);
                    *(__half2*)&tb[r_l * 136 + c_l] =
                        __floats2half2_rn(acc[mt][nt][2 * rr] + sw * mvv.x,
                                          acc[mt][nt][2 * rr + 1] + sw * mvv.y);
                }
            }
        __syncthreads();
#pragma unroll
        for (int i = 0; i < 16; i++) {
            int c = i * 128 + tid;
            int r = c >> 4, off = (c & 15) * 8;
            *(float4*)&H0[(size_t)(b * M_ + m0 + r) * (H_ * P_) + h * P_ + n0 + off] =
                *(float4*)&tb[r * 136 + off];
        }
        return;
    }

#pragma unroll
    for (int mt = 0; mt < 4; mt++)
#pragma unroll
        for (int nt = 0; nt < 8; nt++) {
            int col = n0 + wn * 64 + nt * 8 + 2 * tg;
#pragma unroll
            for (int rr = 0; rr < 2; rr++) {
                int R = m0 + wm * 64 + mt * 16 + g + rr * 8;
                float v0 = acc[mt][nt][2 * rr + 0];
                float v1 = acc[mt][nt][2 * rr + 1];
                if (MODE == 6) {
                    if (part == 0) {
                        if (zz == 0) {
                            float2 bi = *(const float2*)(bias0 + col);
                            *(float2*)&F0[(size_t)R * P_ + col] =
                                make_float2(v0 + bi.x, v1 + bi.y);
                        } else if (zz == 1) {
                            float2 bi = *(const float2*)(bias1 + col);
                            *(float2*)&F1[(size_t)R * P_ + col] =
                                make_float2(v0 + bi.x, v1 + bi.y);
                        } else {
                            int h = zz - 2;
                            float2 bi = *(const float2*)(bias2 + h * P_ + col);
                            int b = R >> 8, m = R & 255;
                            *(__half2*)&H0[(((size_t)(b * H_ + h)) * M_ + m) * P_ + col] =
                                __floats2half2_rn(v0 + bi.x, v1 + bi.y);
                        }
                    } else {  // part==1, zz==0: ik
                        float2 bi = *(const float2*)(bias0 + col);
                        *(__half2*)&H1[(size_t)R * P_ + col] =
                            __floats2half2_rn(v0 + bi.x, v1 + bi.y);
                    }
                } else {  // MODE 5: split-K partial
                    *(float2*)&F0[(size_t)z * (2048 * 512) + (size_t)R * P_ + col] =
                        make_float2(v0, v1);
                }
            }
        }
}

// ---------------- softmax (fused self-score) ---------------------------------
__global__ __launch_bounds__(256) void softmax_fused(
    const __half* __restrict__ scores, __half* __restrict__ probs,
    const __half* __restrict__ q, const float* __restrict__ mk,
    float* __restrict__ selfv)
{
    const int row = blockIdx.x;                 // z*M + m
    const int z = row >> 8, m = row & 255, b = z >> 3;
    const __half* sp = scores + (size_t)row * S_;
    __half* pp = probs + (size_t)row * S_;
    const int tid = threadIdx.x;
    const int lane = tid & 31, wid = tid >> 5;
    __shared__ float red[8];
    __shared__ float svs;

    {
        const __half* qp = q + (size_t)row * P_;
        const float* kp = mk + ((size_t)(b * M_ + m)) * P_;
        __half2 qq = *(const __half2*)(qp + tid * 2);
        float2 kk = *(const float2*)(kp + tid * 2);
        float sd = __low2float(qq) * kk.x + __high2float(qq) * kk.y;
        for (int o = 16; o; o >>= 1) sd += __shfl_xor_sync(0xffffffffu, sd, o);
        if (lane == 0) red[wid] = sd;
        __syncthreads();
        if (tid == 0) {
            float t = 0.f;
            for (int i = 0; i < 8; i++) t += red[i];
            svs = t * SCALE;
        }
        __syncthreads();
    }
    float sv = svs;

    float4 raw = *(const float4*)(sp + tid * 8);
    const __half2* h2 = (const __half2*)&raw;
    float v[8];
#pragma unroll
    for (int i = 0; i < 4; i++) {
        v[2 * i]     = __low2float(h2[i]);
        v[2 * i + 1] = __high2float(h2[i]);
    }
    float vmax = sv;
#pragma unroll
    for (int i = 0; i < 8; i++) vmax = fmaxf(vmax, v[i]);
    for (int o = 16; o; o >>= 1) vmax = fmaxf(vmax, __shfl_xor_sync(0xffffffffu, vmax, o));
    if (lane == 0) red[wid] = vmax;
    __syncthreads();
    if (tid == 0) {
        float t = red[0];
        for (int i = 1; i < 8; i++) t = fmaxf(t, red[i]);
        red[0] = t;
    }
    __syncthreads();
    vmax = red[0];
    __syncthreads();
    float s = 0.f;
#pragma unroll
    for (int i = 0; i < 8; i++) { v[i] = __expf(v[i] - vmax); s += v[i]; }
    float es = __expf(sv - vmax);
    if (tid == 0) s += es;
    for (int o = 16; o; o >>= 1) s += __shfl_xor_sync(0xffffffffu, s, o);
    if (lane == 0) red[wid] = s;
    __syncthreads();
    if (tid == 0) {
        float t = 0.f;
        for (int i = 0; i < 8; i++) t += red[i];
        red[0] = t;
    }
    __syncthreads();
    float inv = 1.0f / red[0];
    float4 outp;
    __half2* o2 = (__half2*)&outp;
#pragma unroll
    for (int i = 0; i < 4; i++)
        o2[i] = __floats2half2_rn(v[2 * i] * inv, v[2 * i + 1] * inv);
    *(float4*)(pp + tid * 8) = outp;
    if (tid == 0) selfv[row] = es * inv;
}

// ---------------- split-K reduction + bias -----------------------------------
__global__ __launch_bounds__(256) void k_reduce_out(
    const float* __restrict__ part, const float* __restrict__ bo,
    float* __restrict__ out)
{
    int idx = (blockIdx.x * 256 + threadIdx.x) * 4;
    float4 a = *(const float4*)(part + idx);
#pragma unroll
    for (int s = 1; s < 4; s++) {
        const float4 p = *(const float4*)(part + (size_t)s * (2048 * 512) + idx);
        a.x += p.x; a.y += p.y; a.z += p.z; a.w += p.w;
    }
    int col = idx & 511;
    float4 b4 = *(const float4*)(bo + col);
    a.x += b4.x; a.y += b4.y; a.z += b4.z; a.w += b4.w;
    *(float4*)(out + idx) = a;
}

// ---------------- launch ----------------------------------------------------
extern "C" void kernel_launch(void* const* d_in, const int* in_sizes, int n_in,
                              void* d_out, int out_size)
{
    const float* input_seq    = (const float*)d_in[0];
    const float* memory_cells = (const float*)d_in[1];
    const float* Wk = (const float*)d_in[2];
    const float* bk = (const float*)d_in[3];
    const float* Wv = (const float*)d_in[4];
    const float* bv = (const float*)d_in[5];
    const float* Wq = (const float*)d_in[6];
    const float* bq = (const float*)d_in[7];
    const float* Wo = (const float*)d_in[8];
    const float* bo = (const float*)d_in[9];
    float* out = (float*)d_out;

    __half *p_inh, *p_memh, *p_ikh, *p_ivTh, *p_qh, *p_sch, *p_prh, *p_cch;
    __half *p_WkT, *p_WvT, *p_WqT, *p_WoT;
    float *p_mk, *p_mv, *p_sf, *p_part;
    cudaGetSymbolAddress((void**)&p_inh,  g_in_h);
    cudaGetSymbolAddress((void**)&p_memh, g_mem_h);
    cudaGetSymbolAddress((void**)&p_ikh,  g_ik_h);
    cudaGetSymbolAddress((void**)&p_ivTh, g_ivT_h);
    cudaGetSymbolAddress((void**)&p_mk,   g_mk);
    cudaGetSymbolAddress((void**)&p_mv,   g_mv);
    cudaGetSymbolAddress((void**)&p_qh,   g_q_h);
    cudaGetSymbolAddress((void**)&p_sch,  g_scores_h);
    cudaGetSymbolAddress((void**)&p_prh,  g_probs_h);
    cudaGetSymbolAddress((void**)&p_sf,   g_self);
    cudaGetSymbolAddress((void**)&p_cch,  g_concat_h);
    cudaGetSymbolAddress((void**)&p_part, g_part);
    cudaGetSymbolAddress((void**)&p_WkT,  g_WkT);
    cudaGetSymbolAddress((void**)&p_WvT,  g_WvT);
    cudaGetSymbolAddress((void**)&p_WqT,  g_WqT);
    cudaGetSymbolAddress((void**)&p_WoT,  g_WoT);

    cudaFuncSetAttribute(gemm_h<6, D_>, cudaFuncAttributeMaxDynamicSharedMemorySize, GEMM_SMEM);
    cudaFuncSetAttribute(gemm_h<2, P_>, cudaFuncAttributeMaxDynamicSharedMemorySize, GEMM_SMEM);
    cudaFuncSetAttribute(gemm_h<3, S_>, cudaFuncAttributeMaxDynamicSharedMemorySize, GEMM_SMEM);
    cudaFuncSetAttribute(gemm_h<5, 1024>, cudaFuncAttributeMaxDynamicSharedMemorySize, GEMM_SMEM);

    // fused prep (tohalf x2 + transposes)
    k_prep<<<13824, 256>>>(input_seq, memory_cells, Wk, Wv, Wq, Wo,
                           p_inh, p_memh, p_WkT, p_WvT, p_WqT, p_WoT);

    // all projections in one launch: mk, mv, q, ik, ivT
    gemm_h<6, D_><<<dim3(4, 416), 128, GEMM_SMEM>>>(
        p_memh, p_inh, p_WkT, p_WvT, p_WqT, bk, bv, bq,
        p_mk, p_mv, p_qh, p_ikh, p_ivTh, nullptr, nullptr);
    // scores -> fp16 (smem-staged epilogue)
    gemm_h<2, P_><<<dim3(16, 2, 64), 128, GEMM_SMEM>>>(
        p_qh, nullptr, p_ikh, nullptr, nullptr, nullptr, nullptr, nullptr,
        nullptr, nullptr, p_sch, nullptr, nullptr, nullptr, nullptr);
    // softmax (+fused self score)
    softmax_fused<<<B_ * H_ * M_, 256>>>(p_sch, p_prh, p_qh, p_mk, p_sf);
    // attn @ V (+ self path) -> concat half (smem-staged epilogue)
    gemm_h<3, S_><<<dim3(4, 2, 64), 128, GEMM_SMEM>>>(
        p_prh, nullptr, p_ivTh, nullptr, nullptr, nullptr, nullptr, nullptr,
        nullptr, nullptr, p_cch, nullptr, nullptr, p_sf, p_mv);
    // output projection: split-K=4 partials + reduce
    gemm_h<5, 1024><<<dim3(4, 16, 4), 128, GEMM_SMEM>>>(
        p_cch, nullptr, p_WoT, nullptr, nullptr, nullptr, nullptr, nullptr,
        p_part, nullptr, nullptr, nullptr, nullptr, nullptr, nullptr);
    k_reduce_out<<<1024, 256>>>(p_part, bo, out);
}

// round 14
// speedup vs baseline: 1.2404x; 1.2404x over previous
#include <cuda_runtime.h>
#include <cuda_fp16.h>
#include <stdint.h>
#include <stddef.h>

#define B_ 8
#define S_ 2048
#define M_ 256
#define D_ 512
#define P_ 512
#define H_ 8
#define SCALE 0.04419417382415922f   // 1/sqrt(512)

// ---------------- scratch (device globals) ----------------------------------
__device__ __half g_in_h[B_ * S_ * D_];
__device__ __half g_mem_h[B_ * M_ * D_];
__device__ __half g_ik_h[B_ * S_ * P_];
__device__ __half g_ivT_h[B_ * P_ * S_];        // transposed V
__device__ float  g_mk[B_ * M_ * P_];
__device__ float  g_mv[B_ * M_ * P_];
__device__ __half g_q_h[B_ * H_ * M_ * P_];     // [b,h,m,p]
__device__ __half g_scores_h[(size_t)B_ * H_ * M_ * S_];
__device__ __half g_probs_h[(size_t)B_ * H_ * M_ * S_];
__device__ float  g_self[B_ * H_ * M_];
__device__ __half g_concat_h[B_ * M_ * H_ * P_];
__device__ float  g_part[4 * 2048 * 512];       // split-K partials
__device__ __half g_WkT[P_ * D_];
__device__ __half g_WvT[P_ * D_];
__device__ __half g_WqT[H_ * P_ * D_];
__device__ __half g_WoT[P_ * H_ * P_];

// ---------------- low-level helpers -----------------------------------------
__device__ __forceinline__ void cpa16(uint32_t s, const void* g) {
    asm volatile("cp.async.cg.shared.global [%0], [%1], 16;\n" ::"r"(s), "l"(g));
}
#define CPA_COMMIT() asm volatile("cp.async.commit_group;\n" ::: "memory")
#define CPA_WAIT1()  asm volatile("cp.async.wait_group 1;\n" ::: "memory")

__device__ __forceinline__ void ldsm4(uint32_t* r, uint32_t addr) {
    asm volatile("ldmatrix.sync.aligned.m8n8.x4.shared.b16 {%0,%1,%2,%3}, [%4];"
        : "=r"(r[0]), "=r"(r[1]), "=r"(r[2]), "=r"(r[3]) : "r"(addr));
}
__device__ __forceinline__ void mma16816(float* d, const uint32_t* a,
                                         uint32_t b0, uint32_t b1) {
    asm volatile(
        "mma.sync.aligned.m16n8k16.row.col.f32.f16.f16.f32 "
        "{%0,%1,%2,%3},{%4,%5,%6,%7},{%8,%9},{%0,%1,%2,%3};"
        : "+f"(d[0]), "+f"(d[1]), "+f"(d[2]), "+f"(d[3])
        : "r"(a[0]), "r"(a[1]), "r"(a[2]), "r"(a[3]), "r"(b0), "r"(b1));
}

// SMEM: BK=64, rows padded to 72 halfs (144B stride -> ldsm conflict-free).
#define ROWP 72
#define STAGE_B (128 * ROWP * 2)
#define GEMM_SMEM (6 * STAGE_B)     // 110592 bytes

// ---------------- fused prep: tohalf(input,mem) + transposes -----------------
__device__ __forceinline__ void transpose_flat(const float* in, __half* out,
                                               int K, int N, int bx, int by,
                                               int tid) {
    __shared__ float t[32][33];
    int k0 = by * 32, n0 = bx * 32;
    int x = tid & 31, y = tid >> 5;   // 32 x 8
#pragma unroll
    for (int i = 0; i < 32; i += 8)
        t[y + i][x] = in[(size_t)(k0 + y + i) * N + n0 + x];
    __syncthreads();
#pragma unroll
    for (int i = 0; i < 32; i += 8)
        out[(size_t)(n0 + y + i) * K + k0 + x] = __float2half(t[x][y + i]);
}
__global__ __launch_bounds__(256) void k_prep(
    const float* __restrict__ input_seq, const float* __restrict__ mem,
    const float* __restrict__ Wk, const float* __restrict__ Wv,
    const float* __restrict__ Wq, const float* __restrict__ Wo,
    __half* __restrict__ in_h, __half* __restrict__ mem_h,
    __half* __restrict__ WkT, __half* __restrict__ WvT,
    __half* __restrict__ WqT, __half* __restrict__ WoT)
{
    int bid = blockIdx.x, tid = threadIdx.x;
    if (bid < 8192) {                 // tohalf input_seq (8M elems)
        size_t i = ((size_t)bid * 256 + tid) * 4;
        float4 v = *(const float4*)(input_seq + i);
        *(__half2*)(in_h + i)     = __floats2half2_rn(v.x, v.y);
        *(__half2*)(in_h + i + 2) = __floats2half2_rn(v.z, v.w);
    } else if (bid < 9216) {          // tohalf memory_cells (1M elems)
        size_t i = ((size_t)(bid - 8192) * 256 + tid) * 4;
        float4 v = *(const float4*)(mem + i);
        *(__half2*)(mem_h + i)     = __floats2half2_rn(v.x, v.y);
        *(__half2*)(mem_h + i + 2) = __floats2half2_rn(v.z, v.w);
    } else if (bid < 11776) {         // Wk/Wv/Wq transposes: 16x16x10
        int t2 = bid - 9216;
        int z = t2 >> 8, rem = t2 & 255;
        int bx = rem & 15, by = rem >> 4;
        const float* in; __half* out;
        if (z == 0)      { in = Wk; out = WkT; }
        else if (z == 1) { in = Wv; out = WvT; }
        else             { in = Wq + (size_t)(z - 2) * D_ * P_;
                           out = WqT + (size_t)(z - 2) * P_ * D_; }
        transpose_flat(in, out, D_, P_, bx, by, tid);
    } else {                          // Wo transpose: 16 x 128
        int t2 = bid - 11776;
        int bx = t2 & 15, by = t2 >> 4;
        transpose_flat(Wo, WoT, H_ * P_, P_, bx, by, tid);
    }
}

// ---------------- fp16 NT GEMM: 128x128 CTA tile, BK=64, 3-stage ------------
// 256 threads, 8 warps (2x4), 64m x 32n per warp. A,B fragments via ldmatrix.
// MODE 6: combined projections. by<160: mem-side (zz: 0->mk f32, 1->mv f32,
//         2..9->q_h scatter); by>=160: input-side (zz: 0->ik_h, 1->ivT_h staged).
// MODE 2: scores -> scores_h fp16 *SCALE (smem-staged)
// MODE 3: val -> concat_h, +self*mv (smem-staged)
// MODE 5: outproj partial -> part[z] f32
template <int MODE, int K>
__global__ __launch_bounds__(256, 2) void gemm_h(
    const __half* __restrict__ A0, const __half* __restrict__ A1,
    const __half* __restrict__ B0, const __half* __restrict__ B1,
    const __half* __restrict__ B2,
    const float* __restrict__ bias0, const float* __restrict__ bias1,
    const float* __restrict__ bias2,
    float* __restrict__ F0, float* __restrict__ F1,
    __half* __restrict__ H0, __half* __restrict__ H1, __half* __restrict__ H2,
    const float* __restrict__ selfw, const float* __restrict__ mvp)
{
    extern __shared__ __align__(16) char smem[];
    const uint32_t sbase = (uint32_t)__cvta_generic_to_shared(smem);
    const uint32_t sB0 = sbase + 3 * STAGE_B;

    const int tid = threadIdx.x;
    const int lane = tid & 31, wid = tid >> 5;
    const int g = lane >> 2, tg = lane & 3;
    const int wm = wid & 1, wn = wid >> 1;
    const int n0 = blockIdx.x * 128;
    const int z = blockIdx.z;
    const int lrow = (lane & 7) + ((lane >> 3) & 1) * 8;
    const int lkb = (lane >> 4) * 8;
    const int bn_local = (lane & 7) + ((lane >> 4) & 1) * 8;
    const int bk_half = ((lane >> 3) & 1) * 8;

    int m0, part = 0, zz = 0;
    if (MODE == 6) {
        int by = blockIdx.y;
        if (by < 160) { part = 0; zz = by >> 4; m0 = (by & 15) * 128; }
        else { int t = by - 160; part = 1; zz = t >> 7; m0 = (t & 127) * 128; }
    } else {
        m0 = blockIdx.y * 128;
    }

    const __half *Ag, *Bg;
    int lda, ldb;
    if (MODE == 6) {
        lda = D_; ldb = D_;
        const __half* Bb;
        if (part == 0) {
            Ag = A0 + (size_t)m0 * lda;
            Bb = (zz == 0) ? B0 : (zz == 1) ? B1 : (B2 + (size_t)(zz - 2) * P_ * D_);
        } else {
            Ag = A1 + (size_t)m0 * lda;
            Bb = (zz == 0) ? B0 : B1;
        }
        Bg = Bb + (size_t)n0 * ldb;
    } else if (MODE == 2) {
        lda = P_; ldb = P_;
        Ag = A0 + (size_t)z * M_ * P_ + (size_t)m0 * lda;
        Bg = B0 + (size_t)(z >> 3) * S_ * P_ + (size_t)n0 * ldb;
    } else if (MODE == 3) {
        lda = S_; ldb = S_;
        Ag = A0 + (size_t)z * M_ * S_ + (size_t)m0 * lda;
        Bg = B0 + (size_t)(z >> 3) * P_ * S_ + (size_t)n0 * ldb;
    } else {  // MODE 5
        lda = H_ * P_; ldb = H_ * P_;
        Ag = A0 + (size_t)m0 * lda + z * 1024;
        Bg = B0 + (size_t)n0 * ldb + z * 1024;
    }

    const int lrw = tid >> 1, hp = tid & 1;
    const __half* gA0 = Ag + (size_t)lrw * lda + hp * 32;
    const __half* gB0 = Bg + (size_t)lrw * ldb + hp * 32;
    const uint32_t dA0 = sbase + (lrw * ROWP + hp * 32) * 2;
    const uint32_t dB0 = sB0 + (lrw * ROWP + hp * 32) * 2;

#define FILL(j) do { \
        int _s = (j) % 3; \
        const __half* _ga = gA0 + (j) * 64; \
        const __half* _gb = gB0 + (j) * 64; \
        uint32_t _da = dA0 + _s * STAGE_B; \
        uint32_t _db = dB0 + _s * STAGE_B; \
        cpa16(_da, _ga);           cpa16(_da + 16, _ga + 8); \
        cpa16(_da + 32, _ga + 16); cpa16(_da + 48, _ga + 24); \
        cpa16(_db, _gb);           cpa16(_db + 16, _gb + 8); \
        cpa16(_db + 32, _gb + 16); cpa16(_db + 48, _gb + 24); \
    } while (0)

    float acc[4][4][4] = {};
    constexpr int NK = K / 64;
    FILL(0); CPA_COMMIT();
    if (NK > 1) { FILL(1); } CPA_COMMIT();
    for (int i = 0; i < NK; i++) {
        CPA_WAIT1();
        __syncthreads();
        if (i + 2 < NK) FILL(i + 2);
        CPA_COMMIT();
        const int s = i % 3;
        const uint32_t aS = sbase + s * STAGE_B;
        const uint32_t bS = sB0 + s * STAGE_B;
#pragma unroll
        for (int kk = 0; kk < 4; kk++) {
            uint32_t a[4][4];
#pragma unroll
            for (int mt = 0; mt < 4; mt++)
                ldsm4(a[mt], aS +
                    ((wm * 64 + mt * 16 + lrow) * ROWP + kk * 16 + lkb) * 2);
#pragma unroll
            for (int np = 0; np < 2; np++) {
                uint32_t br[4];
                ldsm4(br, bS +
                    ((wn * 32 + np * 16 + bn_local) * ROWP + kk * 16 + bk_half) * 2);
#pragma unroll
                for (int mt = 0; mt < 4; mt++) {
                    mma16816(acc[mt][2 * np],     a[mt], br[0], br[1]);
                    mma16816(acc[mt][2 * np + 1], a[mt], br[2], br[3]);
                }
            }
        }
    }
#undef FILL

    // ---- ivT path: SMEM-staged transpose, coalesced stores ----
    if (MODE == 6 && part == 1 && zz == 1) {
        __syncthreads();
        __half* tb = (__half*)smem;           // [128 p][136 s-pad]
#pragma unroll
        for (int mt = 0; mt < 4; mt++)
#pragma unroll
            for (int nt = 0; nt < 4; nt++) {
                int p_l = wn * 32 + nt * 8 + 2 * tg;
                float2 bi = *(const float2*)(bias1 + n0 + p_l);
#pragma unroll
                for (int rr = 0; rr < 2; rr++) {
                    int s_l = wm * 64 + mt * 16 + g + rr * 8;
                    tb[(p_l)     * 136 + s_l] = __float2half(acc[mt][nt][2 * rr] + bi.x);
                    tb[(p_l + 1) * 136 + s_l] = __float2half(acc[mt][nt][2 * rr + 1] + bi.y);
                }
            }
        __syncthreads();
        int b = m0 >> 11, s0 = m0 & 2047;
#pragma unroll
        for (int i = 0; i < 8; i++) {
            int c = i * 256 + tid;
            int p = c >> 4, off = (c & 15) * 8;
            *(float4*)&H2[((size_t)b * P_ + n0 + p) * S_ + s0 + off] =
                *(float4*)&tb[p * 136 + off];
        }
        return;
    }

    // ---- scores path: SMEM-staged, coalesced stores ----
    if (MODE == 2) {
        __syncthreads();
        __half* tb = (__half*)smem;           // [128 m][136 s-pad]
#pragma unroll
        for (int mt = 0; mt < 4; mt++)
#pragma unroll
            for (int nt = 0; nt < 4; nt++) {
                int c_l = wn * 32 + nt * 8 + 2 * tg;
#pragma unroll
                for (int rr = 0; rr < 2; rr++) {
                    int r_l = wm * 64 + mt * 16 + g + rr * 8;
                    *(__half2*)&tb[r_l * 136 + c_l] =
                        __floats2half2_rn(acc[mt][nt][2 * rr] * SCALE,
                                          acc[mt][nt][2 * rr + 1] * SCALE);
                }
            }
        __syncthreads();
#pragma unroll
        for (int i = 0; i < 8; i++) {
            int c = i * 256 + tid;
            int r = c >> 4, off = (c & 15) * 8;
            *(float4*)&H0[((size_t)z * M_ + m0 + r) * S_ + n0 + off] =
                *(float4*)&tb[r * 136 + off];
        }
        return;
    }

    // ---- val path: SMEM-staged (+self*mv), coalesced stores ----
    if (MODE == 3) {
        __syncthreads();
        __half* tb = (__half*)smem;           // [128 m][136 p-pad]
        int b = z >> 3, h = z & 7;
#pragma unroll
        for (int mt = 0; mt < 4; mt++)
#pragma unroll
            for (int nt = 0; nt < 4; nt++) {
                int c_l = wn * 32 + nt * 8 + 2 * tg;
#pragma unroll
                for (int rr = 0; rr < 2; rr++) {
                    int r_l = wm * 64 + mt * 16 + g + rr * 8;
                    int R = m0 + r_l;
                    float sw = selfw[(size_t)z * M_ + R];
                    float2 mvv = *(const float2*)(mvp +
                        ((size_t)(b * M_ + R)) * P_ + n0 + c_l);
                    *(__half2*)&tb[r_l * 136 + c_l] =
                        __floats2half2_rn(acc[mt][nt][2 * rr] + sw * mvv.x,
                                          acc[mt][nt][2 * rr + 1] + sw * mvv.y);
                }
            }
        __syncthreads();
#pragma unroll
        for (int i = 0; i < 8; i++) {
            int c = i * 256 + tid;
            int r = c >> 4, off = (c & 15) * 8;
            *(float4*)&H0[(size_t)(b * M_ + m0 + r) * (H_ * P_) + h * P_ + n0 + off] =
                *(float4*)&tb[r * 136 + off];
        }
        return;
    }

#pragma unroll
    for (int mt = 0; mt < 4; mt++)
#pragma unroll
        for (int nt = 0; nt < 4; nt++) {
            int col = n0 + wn * 32 + nt * 8 + 2 * tg;
#pragma unroll
            for (int rr = 0; rr < 2; rr++) {
                int R = m0 + wm * 64 + mt * 16 + g + rr * 8;
                float v0 = acc[mt][nt][2 * rr + 0];
                float v1 = acc[mt][nt][2 * rr + 1];
                if (MODE == 6) {
                    if (part == 0) {
                        if (zz == 0) {
                            float2 bi = *(const float2*)(bias0 + col);
                            *(float2*)&F0[(size_t)R * P_ + col] =
                                make_float2(v0 + bi.x, v1 + bi.y);
                        } else if (zz == 1) {
                            float2 bi = *(const float2*)(bias1 + col);
                            *(float2*)&F1[(size_t)R * P_ + col] =
                                make_float2(v0 + bi.x, v1 + bi.y);
                        } else {
                            int h = zz - 2;
                            float2 bi = *(const float2*)(bias2 + h * P_ + col);
                            int b = R >> 8, m = R & 255;
                            *(__half2*)&H0[(((size_t)(b * H_ + h)) * M_ + m) * P_ + col] =
                                __floats2half2_rn(v0 + bi.x, v1 + bi.y);
                        }
                    } else {  // part==1, zz==0: ik
                        float2 bi = *(const float2*)(bias0 + col);
                        *(__half2*)&H1[(size_t)R * P_ + col] =
                            __floats2half2_rn(v0 + bi.x, v1 + bi.y);
                    }
                } else {  // MODE 5: split-K partial
                    *(float2*)&F0[(size_t)z * (2048 * 512) + (size_t)R * P_ + col] =
                        make_float2(v0, v1);
                }
            }
        }
}

// ---------------- softmax (fused self-score) ---------------------------------
__global__ __launch_bounds__(256) void softmax_fused(
    const __half* __restrict__ scores, __half* __restrict__ probs,
    const __half* __restrict__ q, const float* __restrict__ mk,
    float* __restrict__ selfv)
{
    const int row = blockIdx.x;                 // z*M + m
    const int z = row >> 8, m = row & 255, b = z >> 3;
    const __half* sp = scores + (size_t)row * S_;
    __half* pp = probs + (size_t)row * S_;
    const int tid = threadIdx.x;
    const int lane = tid & 31, wid = tid >> 5;
    __shared__ float red[8];
    __shared__ float svs;

    {
        const __half* qp = q + (size_t)row * P_;
        const float* kp = mk + ((size_t)(b * M_ + m)) * P_;
        __half2 qq = *(const __half2*)(qp + tid * 2);
        float2 kk = *(const float2*)(kp + tid * 2);
        float sd = __low2float(qq) * kk.x + __high2float(qq) * kk.y;
        for (int o = 16; o; o >>= 1) sd += __shfl_xor_sync(0xffffffffu, sd, o);
        if (lane == 0) red[wid] = sd;
        __syncthreads();
        if (tid == 0) {
            float t = 0.f;
            for (int i = 0; i < 8; i++) t += red[i];
            svs = t * SCALE;
        }
        __syncthreads();
    }
    float sv = svs;

    float4 raw = *(const float4*)(sp + tid * 8);
    const __half2* h2 = (const __half2*)&raw;
    float v[8];
#pragma unroll
    for (int i = 0; i < 4; i++) {
        v[2 * i]     = __low2float(h2[i]);
        v[2 * i + 1] = __high2float(h2[i]);
    }
    float vmax = sv;
#pragma unroll
    for (int i = 0; i < 8; i++) vmax = fmaxf(vmax, v[i]);
    for (int o = 16; o; o >>= 1) vmax = fmaxf(vmax, __shfl_xor_sync(0xffffffffu, vmax, o));
    if (lane == 0) red[wid] = vmax;
    __syncthreads();
    if (tid == 0) {
        float t = red[0];
        for (int i = 1; i < 8; i++) t = fmaxf(t, red[i]);
        red[0] = t;
    }
    __syncthreads();
    vmax = red[0];
    __syncthreads();
    float s = 0.f;
#pragma unroll
    for (int i = 0; i < 8; i++) { v[i] = __expf(v[i] - vmax); s += v[i]; }
    float es = __expf(sv - vmax);
    if (tid == 0) s += es;
    for (int o = 16; o; o >>= 1) s += __shfl_xor_sync(0xffffffffu, s, o);
    if (lane == 0) red[wid] = s;
    __syncthreads();
    if (tid == 0) {
        float t = 0.f;
        for (int i = 0; i < 8; i++) t += red[i];
        red[0] = t;
    }
    __syncthreads();
    float inv = 1.0f / red[0];
    float4 outp;
    __half2* o2 = (__half2*)&outp;
#pragma unroll
    for (int i = 0; i < 4; i++)
        o2[i] = __floats2half2_rn(v[2 * i] * inv, v[2 * i + 1] * inv);
    *(float4*)(pp + tid * 8) = outp;
    if (tid == 0) selfv[row] = es * inv;
}

// ---------------- split-K reduction + bias -----------------------------------
__global__ __launch_bounds__(256) void k_reduce_out(
    const float* __restrict__ part, const float* __restrict__ bo,
    float* __restrict__ out)
{
    int idx = (blockIdx.x * 256 + threadIdx.x) * 4;
    float4 a = *(const float4*)(part + idx);
#pragma unroll
    for (int s = 1; s < 4; s++) {
        const float4 p = *(const float4*)(part + (size_t)s * (2048 * 512) + idx);
        a.x += p.x; a.y += p.y; a.z += p.z; a.w += p.w;
    }
    int col = idx & 511;
    float4 b4 = *(const float4*)(bo + col);
    a.x += b4.x; a.y += b4.y; a.z += b4.z; a.w += b4.w;
    *(float4*)(out + idx) = a;
}

// ---------------- launch ----------------------------------------------------
extern "C" void kernel_launch(void* const* d_in, const int* in_sizes, int n_in,
                              void* d_out, int out_size)
{
    const float* input_seq    = (const float*)d_in[0];
    const float* memory_cells = (const float*)d_in[1];
    const float* Wk = (const float*)d_in[2];
    const float* bk = (const float*)d_in[3];
    const float* Wv = (const float*)d_in[4];
    const float* bv = (const float*)d_in[5];
    const float* Wq = (const float*)d_in[6];
    const float* bq = (const float*)d_in[7];
    const float* Wo = (const float*)d_in[8];
    const float* bo = (const float*)d_in[9];
    float* out = (float*)d_out;

    __half *p_inh, *p_memh, *p_ikh, *p_ivTh, *p_qh, *p_sch, *p_prh, *p_cch;
    __half *p_WkT, *p_WvT, *p_WqT, *p_WoT;
    float *p_mk, *p_mv, *p_sf, *p_part;
    cudaGetSymbolAddress((void**)&p_inh,  g_in_h);
    cudaGetSymbolAddress((void**)&p_memh, g_mem_h);
    cudaGetSymbolAddress((void**)&p_ikh,  g_ik_h);
    cudaGetSymbolAddress((void**)&p_ivTh, g_ivT_h);
    cudaGetSymbolAddress((void**)&p_mk,   g_mk);
    cudaGetSymbolAddress((void**)&p_mv,   g_mv);
    cudaGetSymbolAddress((void**)&p_qh,   g_q_h);
    cudaGetSymbolAddress((void**)&p_sch,  g_scores_h);
    cudaGetSymbolAddress((void**)&p_prh,  g_probs_h);
    cudaGetSymbolAddress((void**)&p_sf,   g_self);
    cudaGetSymbolAddress((void**)&p_cch,  g_concat_h);
    cudaGetSymbolAddress((void**)&p_part, g_part);
    cudaGetSymbolAddress((void**)&p_WkT,  g_WkT);
    cudaGetSymbolAddress((void**)&p_WvT,  g_WvT);
    cudaGetSymbolAddress((void**)&p_WqT,  g_WqT);
    cudaGetSymbolAddress((void**)&p_WoT,  g_WoT);

    cudaFuncSetAttribute(gemm_h<6, D_>, cudaFuncAttributeMaxDynamicSharedMemorySize, GEMM_SMEM);
    cudaFuncSetAttribute(gemm_h<2, P_>, cudaFuncAttributeMaxDynamicSharedMemorySize, GEMM_SMEM);
    cudaFuncSetAttribute(gemm_h<3, S_>, cudaFuncAttributeMaxDynamicSharedMemorySize, GEMM_SMEM);
    cudaFuncSetAttribute(gemm_h<5, 1024>, cudaFuncAttributeMaxDynamicSharedMemorySize, GEMM_SMEM);

    // fused prep (tohalf x2 + all weight transposes), one launch
    k_prep<<<13824, 256>>>(input_seq, memory_cells, Wk, Wv, Wq, Wo,
                           p_inh, p_memh, p_WkT, p_WvT, p_WqT, p_WoT);

    // all projections in one launch: mk, mv, q, ik, ivT
    gemm_h<6, D_><<<dim3(4, 416), 256, GEMM_SMEM>>>(
        p_memh, p_inh, p_WkT, p_WvT, p_WqT, bk, bv, bq,
        p_mk, p_mv, p_qh, p_ikh, p_ivTh, nullptr, nullptr);
    // scores -> fp16 (smem-staged epilogue)
    gemm_h<2, P_><<<dim3(16, 2, 64), 256, GEMM_SMEM>>>(
        p_qh, nullptr, p_ikh, nullptr, nullptr, nullptr, nullptr, nullptr,
        nullptr, nullptr, p_sch, nullptr, nullptr, nullptr, nullptr);
    // softmax (+fused self score)
    softmax_fused<<<B_ * H_ * M_, 256>>>(p_sch, p_prh, p_qh, p_mk, p_sf);
    // attn @ V (+ self path) -> concat half (smem-staged epilogue)
    gemm_h<3, S_><<<dim3(4, 2, 64), 256, GEMM_SMEM>>>(
        p_prh, nullptr, p_ivTh, nullptr, nullptr, nullptr, nullptr, nullptr,
        nullptr, nullptr, p_cch, nullptr, nullptr, p_sf, p_mv);
    // output projection: split-K=4 partials + reduce
    gemm_h<5, 1024><<<dim3(4, 16, 4), 256, GEMM_SMEM>>>(
        p_cch, nullptr, p_WoT, nullptr, nullptr, nullptr, nullptr, nullptr,
        p_part, nullptr, nullptr, nullptr, nullptr, nullptr, nullptr);
    k_reduce_out<<<1024, 256>>>(p_part, bo, out);
}

// round 15
// speedup vs baseline: 1.2554x; 1.0121x over previous
#include <cuda_runtime.h>
#include <cuda_fp16.h>
#include <stdint.h>
#include <stddef.h>

#define B_ 8
#define S_ 2048
#define M_ 256
#define D_ 512
#define P_ 512
#define H_ 8
#define SCALE 0.04419417382415922f   // 1/sqrt(512)

// ---------------- scratch (device globals) ----------------------------------
__device__ __half g_in_h[B_ * S_ * D_];
__device__ __half g_mem_h[B_ * M_ * D_];
__device__ __half g_ik_h[B_ * S_ * P_];
__device__ __half g_ivT_h[B_ * P_ * S_];        // transposed V
__device__ float  g_mk[B_ * M_ * P_];
__device__ float  g_mv[B_ * M_ * P_];
__device__ __half g_q_h[B_ * H_ * M_ * P_];     // [b,h,m,p]
__device__ __half g_scores_h[(size_t)B_ * H_ * M_ * S_];
__device__ __half g_probs_h[(size_t)B_ * H_ * M_ * S_];
__device__ float  g_self[B_ * H_ * M_];
__device__ __half g_concat_h[B_ * M_ * H_ * P_];
__device__ float  g_part[4 * 2048 * 512];       // split-K partials
__device__ __half g_WkT[P_ * D_];
__device__ __half g_WvT[P_ * D_];
__device__ __half g_WqT[H_ * P_ * D_];
__device__ __half g_WoT[P_ * H_ * P_];

// ---------------- low-level helpers -----------------------------------------
__device__ __forceinline__ void cpa16(uint32_t s, const void* g) {
    asm volatile("cp.async.cg.shared.global [%0], [%1], 16;\n" ::"r"(s), "l"(g));
}
#define CPA_COMMIT() asm volatile("cp.async.commit_group;\n" ::: "memory")
#define CPA_WAIT1()  asm volatile("cp.async.wait_group 1;\n" ::: "memory")

__device__ __forceinline__ void ldsm4(uint32_t* r, uint32_t addr) {
    asm volatile("ldmatrix.sync.aligned.m8n8.x4.shared.b16 {%0,%1,%2,%3}, [%4];"
        : "=r"(r[0]), "=r"(r[1]), "=r"(r[2]), "=r"(r[3]) : "r"(addr));
}
__device__ __forceinline__ void mma16816(float* d, const uint32_t* a,
                                         uint32_t b0, uint32_t b1) {
    asm volatile(
        "mma.sync.aligned.m16n8k16.row.col.f32.f16.f16.f32 "
        "{%0,%1,%2,%3},{%4,%5,%6,%7},{%8,%9},{%0,%1,%2,%3};"
        : "+f"(d[0]), "+f"(d[1]), "+f"(d[2]), "+f"(d[3])
        : "r"(a[0]), "r"(a[1]), "r"(a[2]), "r"(a[3]), "r"(b0), "r"(b1));
}

// SMEM: BK=64, rows padded to 72 halfs (144B stride -> ldsm conflict-free).
#define ROWP 72
#define STAGE_B (128 * ROWP * 2)
#define GEMM_SMEM (6 * STAGE_B)     // 110592 bytes

// ---------------- fused prep: tohalf(input,mem) + transposes -----------------
__device__ __forceinline__ void transpose_flat(const float* in, __half* out,
                                               int K, int N, int bx, int by,
                                               int tid) {
    __shared__ float t[32][33];
    int k0 = by * 32, n0 = bx * 32;
    int x = tid & 31, y = tid >> 5;   // 32 x 8
#pragma unroll
    for (int i = 0; i < 32; i += 8)
        t[y + i][x] = in[(size_t)(k0 + y + i) * N + n0 + x];
    __syncthreads();
#pragma unroll
    for (int i = 0; i < 32; i += 8)
        out[(size_t)(n0 + y + i) * K + k0 + x] = __float2half(t[x][y + i]);
}
__global__ __launch_bounds__(256) void k_prep(
    const float* __restrict__ input_seq, const float* __restrict__ mem,
    const float* __restrict__ Wk, const float* __restrict__ Wv,
    const float* __restrict__ Wq, const float* __restrict__ Wo,
    __half* __restrict__ in_h, __half* __restrict__ mem_h,
    __half* __restrict__ WkT, __half* __restrict__ WvT,
    __half* __restrict__ WqT, __half* __restrict__ WoT)
{
    int bid = blockIdx.x, tid = threadIdx.x;
    if (bid < 8192) {                 // tohalf input_seq
        size_t i = ((size_t)bid * 256 + tid) * 4;
        float4 v = *(const float4*)(input_seq + i);
        *(__half2*)(in_h + i)     = __floats2half2_rn(v.x, v.y);
        *(__half2*)(in_h + i + 2) = __floats2half2_rn(v.z, v.w);
    } else if (bid < 9216) {          // tohalf memory_cells
        size_t i = ((size_t)(bid - 8192) * 256 + tid) * 4;
        float4 v = *(const float4*)(mem + i);
        *(__half2*)(mem_h + i)     = __floats2half2_rn(v.x, v.y);
        *(__half2*)(mem_h + i + 2) = __floats2half2_rn(v.z, v.w);
    } else if (bid < 11776) {         // Wk/Wv/Wq transposes: 16x16x10
        int t2 = bid - 9216;
        int z = t2 >> 8, rem = t2 & 255;
        int bx = rem & 15, by = rem >> 4;
        const float* in; __half* out;
        if (z == 0)      { in = Wk; out = WkT; }
        else if (z == 1) { in = Wv; out = WvT; }
        else             { in = Wq + (size_t)(z - 2) * D_ * P_;
                           out = WqT + (size_t)(z - 2) * P_ * D_; }
        transpose_flat(in, out, D_, P_, bx, by, tid);
    } else {                          // Wo transpose: 16 x 128
        int t2 = bid - 11776;
        int bx = t2 & 15, by = t2 >> 4;
        transpose_flat(Wo, WoT, H_ * P_, P_, bx, by, tid);
    }
}

// ---------------- fp16 NT GEMM: 128x128 CTA tile, BK=64, 3-stage ------------
// 256 threads, 8 warps (2x4), 64m x 32n per warp. A,B fragments via ldmatrix.
template <int MODE, int K>
__global__ __launch_bounds__(256, 2) void gemm_h(
    const __half* __restrict__ A0, const __half* __restrict__ A1,
    const __half* __restrict__ B0, const __half* __restrict__ B1,
    const __half* __restrict__ B2,
    const float* __restrict__ bias0, const float* __restrict__ bias1,
    const float* __restrict__ bias2,
    float* __restrict__ F0, float* __restrict__ F1,
    __half* __restrict__ H0, __half* __restrict__ H1, __half* __restrict__ H2,
    const float* __restrict__ selfw, const float* __restrict__ mvp)
{
    extern __shared__ __align__(16) char smem[];
    const uint32_t sbase = (uint32_t)__cvta_generic_to_shared(smem);
    const uint32_t sB0 = sbase + 3 * STAGE_B;

    const int tid = threadIdx.x;
    const int lane = tid & 31, wid = tid >> 5;
    const int g = lane >> 2, tg = lane & 3;
    const int wm = wid & 1, wn = wid >> 1;
    const int n0 = blockIdx.x * 128;
    const int z = blockIdx.z;
    const int lrow = (lane & 7) + ((lane >> 3) & 1) * 8;
    const int lkb = (lane >> 4) * 8;
    const int bn_local = (lane & 7) + ((lane >> 4) & 1) * 8;
    const int bk_half = ((lane >> 3) & 1) * 8;

    int m0, part = 0, zz = 0;
    if (MODE == 6) {
        int by = blockIdx.y;
        if (by < 160) { part = 0; zz = by >> 4; m0 = (by & 15) * 128; }
        else { int t = by - 160; part = 1; zz = t >> 7; m0 = (t & 127) * 128; }
    } else {
        m0 = blockIdx.y * 128;
    }

    const __half *Ag, *Bg;
    int lda, ldb;
    if (MODE == 6) {
        lda = D_; ldb = D_;
        const __half* Bb;
        if (part == 0) {
            Ag = A0 + (size_t)m0 * lda;
            Bb = (zz == 0) ? B0 : (zz == 1) ? B1 : (B2 + (size_t)(zz - 2) * P_ * D_);
        } else {
            Ag = A1 + (size_t)m0 * lda;
            Bb = (zz == 0) ? B0 : B1;
        }
        Bg = Bb + (size_t)n0 * ldb;
    } else if (MODE == 2) {
        lda = P_; ldb = P_;
        Ag = A0 + (size_t)z * M_ * P_ + (size_t)m0 * lda;
        Bg = B0 + (size_t)(z >> 3) * S_ * P_ + (size_t)n0 * ldb;
    } else if (MODE == 3) {
        lda = S_; ldb = S_;
        Ag = A0 + (size_t)z * M_ * S_ + (size_t)m0 * lda;
        Bg = B0 + (size_t)(z >> 3) * P_ * S_ + (size_t)n0 * ldb;
    } else {  // MODE 5
        lda = H_ * P_; ldb = H_ * P_;
        Ag = A0 + (size_t)m0 * lda + z * 1024;
        Bg = B0 + (size_t)n0 * ldb + z * 1024;
    }

    const int lrw = tid >> 1, hp = tid & 1;
    const __half* gA0 = Ag + (size_t)lrw * lda + hp * 32;
    const __half* gB0 = Bg + (size_t)lrw * ldb + hp * 32;
    const uint32_t dA0 = sbase + (lrw * ROWP + hp * 32) * 2;
    const uint32_t dB0 = sB0 + (lrw * ROWP + hp * 32) * 2;

#define FILL(j) do { \
        int _s = (j) % 3; \
        const __half* _ga = gA0 + (j) * 64; \
        const __half* _gb = gB0 + (j) * 64; \
        uint32_t _da = dA0 + _s * STAGE_B; \
        uint32_t _db = dB0 + _s * STAGE_B; \
        cpa16(_da, _ga);           cpa16(_da + 16, _ga + 8); \
        cpa16(_da + 32, _ga + 16); cpa16(_da + 48, _ga + 24); \
        cpa16(_db, _gb);           cpa16(_db + 16, _gb + 8); \
        cpa16(_db + 32, _gb + 16); cpa16(_db + 48, _gb + 24); \
    } while (0)

    float acc[4][4][4] = {};
    constexpr int NK = K / 64;
    FILL(0); CPA_COMMIT();
    if (NK > 1) { FILL(1); } CPA_COMMIT();
    for (int i = 0; i < NK; i++) {
        CPA_WAIT1();
        __syncthreads();
        if (i + 2 < NK) FILL(i + 2);
        CPA_COMMIT();
        const int s = i % 3;
        const uint32_t aS = sbase + s * STAGE_B;
        const uint32_t bS = sB0 + s * STAGE_B;
#pragma unroll
        for (int kk = 0; kk < 4; kk++) {
            uint32_t a[4][4];
#pragma unroll
            for (int mt = 0; mt < 4; mt++)
                ldsm4(a[mt], aS +
                    ((wm * 64 + mt * 16 + lrow) * ROWP + kk * 16 + lkb) * 2);
#pragma unroll
            for (int np = 0; np < 2; np++) {
                uint32_t br[4];
                ldsm4(br, bS +
                    ((wn * 32 + np * 16 + bn_local) * ROWP + kk * 16 + bk_half) * 2);
#pragma unroll
                for (int mt = 0; mt < 4; mt++) {
                    mma16816(acc[mt][2 * np],     a[mt], br[0], br[1]);
                    mma16816(acc[mt][2 * np + 1], a[mt], br[2], br[3]);
                }
            }
        }
    }
#undef FILL

    // ---- ivT path: SMEM-staged transpose, coalesced stores ----
    if (MODE == 6 && part == 1 && zz == 1) {
        __syncthreads();
        __half* tb = (__half*)smem;           // [128 p][136 s-pad]
#pragma unroll
        for (int mt = 0; mt < 4; mt++)
#pragma unroll
            for (int nt = 0; nt < 4; nt++) {
                int p_l = wn * 32 + nt * 8 + 2 * tg;
                float2 bi = *(const float2*)(bias1 + n0 + p_l);
#pragma unroll
                for (int rr = 0; rr < 2; rr++) {
                    int s_l = wm * 64 + mt * 16 + g + rr * 8;
                    tb[(p_l)     * 136 + s_l] = __float2half(acc[mt][nt][2 * rr] + bi.x);
                    tb[(p_l + 1) * 136 + s_l] = __float2half(acc[mt][nt][2 * rr + 1] + bi.y);
                }
            }
        __syncthreads();
        int b = m0 >> 11, s0 = m0 & 2047;
#pragma unroll
        for (int i = 0; i < 8; i++) {
            int c = i * 256 + tid;
            int p = c >> 4, off = (c & 15) * 8;
            *(float4*)&H2[((size_t)b * P_ + n0 + p) * S_ + s0 + off] =
                *(float4*)&tb[p * 136 + off];
        }
        return;
    }

    // ---- scores path: SMEM-staged, coalesced stores ----
    if (MODE == 2) {
        __syncthreads();
        __half* tb = (__half*)smem;           // [128 m][136 s-pad]
#pragma unroll
        for (int mt = 0; mt < 4; mt++)
#pragma unroll
            for (int nt = 0; nt < 4; nt++) {
                int c_l = wn * 32 + nt * 8 + 2 * tg;
#pragma unroll
                for (int rr = 0; rr < 2; rr++) {
                    int r_l = wm * 64 + mt * 16 + g + rr * 8;
                    *(__half2*)&tb[r_l * 136 + c_l] =
                        __floats2half2_rn(acc[mt][nt][2 * rr] * SCALE,
                                          acc[mt][nt][2 * rr + 1] * SCALE);
                }
            }
        __syncthreads();
#pragma unroll
        for (int i = 0; i < 8; i++) {
            int c = i * 256 + tid;
            int r = c >> 4, off = (c & 15) * 8;
            *(float4*)&H0[((size_t)z * M_ + m0 + r) * S_ + n0 + off] =
                *(float4*)&tb[r * 136 + off];
        }
        return;
    }

    // ---- val path: SMEM-staged (+self*mv), coalesced stores ----
    if (MODE == 3) {
        __syncthreads();
        __half* tb = (__half*)smem;           // [128 m][136 p-pad]
        int b = z >> 3, h = z & 7;
#pragma unroll
        for (int mt = 0; mt < 4; mt++)
#pragma unroll
            for (int nt = 0; nt < 4; nt++) {
                int c_l = wn * 32 + nt * 8 + 2 * tg;
#pragma unroll
                for (int rr = 0; rr < 2; rr++) {
                    int r_l = wm * 64 + mt * 16 + g + rr * 8;
                    int R = m0 + r_l;
                    float sw = selfw[(size_t)z * M_ + R];
                    float2 mvv = *(const float2*)(mvp +
                        ((size_t)(b * M_ + R)) * P_ + n0 + c_l);
                    *(__half2*)&tb[r_l * 136 + c_l] =
                        __floats2half2_rn(acc[mt][nt][2 * rr] + sw * mvv.x,
                                          acc[mt][nt][2 * rr + 1] + sw * mvv.y);
                }
            }
        __syncthreads();
#pragma unroll
        for (int i = 0; i < 8; i++) {
            int c = i * 256 + tid;
            int r = c >> 4, off = (c & 15) * 8;
            *(float4*)&H0[(size_t)(b * M_ + m0 + r) * (H_ * P_) + h * P_ + n0 + off] =
                *(float4*)&tb[r * 136 + off];
        }
        return;
    }

#pragma unroll
    for (int mt = 0; mt < 4; mt++)
#pragma unroll
        for (int nt = 0; nt < 4; nt++) {
            int col = n0 + wn * 32 + nt * 8 + 2 * tg;
#pragma unroll
            for (int rr = 0; rr < 2; rr++) {
                int R = m0 + wm * 64 + mt * 16 + g + rr * 8;
                float v0 = acc[mt][nt][2 * rr + 0];
                float v1 = acc[mt][nt][2 * rr + 1];
                if (MODE == 6) {
                    if (part == 0) {
                        if (zz == 0) {
                            float2 bi = *(const float2*)(bias0 + col);
                            *(float2*)&F0[(size_t)R * P_ + col] =
                                make_float2(v0 + bi.x, v1 + bi.y);
                        } else if (zz == 1) {
                            float2 bi = *(const float2*)(bias1 + col);
                            *(float2*)&F1[(size_t)R * P_ + col] =
                                make_float2(v0 + bi.x, v1 + bi.y);
                        } else {
                            int h = zz - 2;
                            float2 bi = *(const float2*)(bias2 + h * P_ + col);
                            int b = R >> 8, m = R & 255;
                            *(__half2*)&H0[(((size_t)(b * H_ + h)) * M_ + m) * P_ + col] =
                                __floats2half2_rn(v0 + bi.x, v1 + bi.y);
                        }
                    } else {  // part==1, zz==0: ik
                        float2 bi = *(const float2*)(bias0 + col);
                        *(__half2*)&H1[(size_t)R * P_ + col] =
                            __floats2half2_rn(v0 + bi.x, v1 + bi.y);
                    }
                } else {  // MODE 5: split-K partial
                    *(float2*)&F0[(size_t)z * (2048 * 512) + (size_t)R * P_ + col] =
                        make_float2(v0, v1);
                }
            }
        }
}

// ---------------- warp-per-row softmax (fused self-score) --------------------
// 256 threads = 8 warps; warp w owns row blockIdx.x*8+w. No barriers, no smem.
__global__ __launch_bounds__(256) void softmax_warp(
    const __half* __restrict__ scores, __half* __restrict__ probs,
    const __half* __restrict__ q, const float* __restrict__ mk,
    float* __restrict__ selfv)
{
    const int wid = threadIdx.x >> 5, lane = threadIdx.x & 31;
    const int row = blockIdx.x * 8 + wid;       // z*M + m
    const int z = row >> 8, m = row & 255, b = z >> 3;

    // ---- self score: dot(q[row], mk[b,m]) * SCALE, warp-reduced ----
    float sd = 0.f;
    {
        const float4* q4 = (const float4*)(q + (size_t)row * P_);      // 64 f4
        const float4* k4 = (const float4*)(mk + ((size_t)(b * M_ + m)) * P_);
#pragma unroll
        for (int j = 0; j < 2; j++) {
            int idx = lane + j * 32;
            float4 qf = q4[idx];
            const __half2* qh = (const __half2*)&qf;
            float4 ka = k4[2 * idx], kb = k4[2 * idx + 1];
            sd += __low2float(qh[0]) * ka.x + __high2float(qh[0]) * ka.y
                + __low2float(qh[1]) * ka.z + __high2float(qh[1]) * ka.w
                + __low2float(qh[2]) * kb.x + __high2float(qh[2]) * kb.y
                + __low2float(qh[3]) * kb.z + __high2float(qh[3]) * kb.w;
        }
        for (int o = 16; o; o >>= 1) sd += __shfl_xor_sync(0xffffffffu, sd, o);
        sd *= SCALE;
    }

    // ---- load 64 scores per lane (8 x float4 of halfs), max, exp, sum ----
    const float4* sp4 = (const float4*)(scores + (size_t)row * S_);    // 256 f4
    float4* pp4 = (float4*)(probs + (size_t)row * S_);
    float v[64];
#pragma unroll
    for (int j = 0; j < 8; j++) {
        float4 raw = sp4[lane + j * 32];
        const __half2* h2 = (const __half2*)&raw;
#pragma unroll
        for (int i = 0; i < 4; i++) {
            v[j * 8 + 2 * i]     = __low2float(h2[i]);
            v[j * 8 + 2 * i + 1] = __high2float(h2[i]);
        }
    }
    float vmax = sd;
#pragma unroll
    for (int i = 0; i < 64; i++) vmax = fmaxf(vmax, v[i]);
    for (int o = 16; o; o >>= 1) vmax = fmaxf(vmax, __shfl_xor_sync(0xffffffffu, vmax, o));

    float s = 0.f;
#pragma unroll
    for (int i = 0; i < 64; i++) { v[i] = __expf(v[i] - vmax); s += v[i]; }
    float es = __expf(sd - vmax);
    if (lane == 0) s += es;
    for (int o = 16; o; o >>= 1) s += __shfl_xor_sync(0xffffffffu, s, o);
    float inv = 1.0f / s;

#pragma unroll
    for (int j = 0; j < 8; j++) {
        float4 outp;
        __half2* o2 = (__half2*)&outp;
#pragma unroll
        for (int i = 0; i < 4; i++)
            o2[i] = __floats2half2_rn(v[j * 8 + 2 * i] * inv,
                                      v[j * 8 + 2 * i + 1] * inv);
        pp4[lane + j * 32] = outp;
    }
    if (lane == 0) selfv[row] = es * inv;
}

// ---------------- split-K reduction + bias -----------------------------------
__global__ __launch_bounds__(256) void k_reduce_out(
    const float* __restrict__ part, const float* __restrict__ bo,
    float* __restrict__ out)
{
    int idx = (blockIdx.x * 256 + threadIdx.x) * 4;
    float4 a = *(const float4*)(part + idx);
#pragma unroll
    for (int s = 1; s < 4; s++) {
        const float4 p = *(const float4*)(part + (size_t)s * (2048 * 512) + idx);
        a.x += p.x; a.y += p.y; a.z += p.z; a.w += p.w;
    }
    int col = idx & 511;
    float4 b4 = *(const float4*)(bo + col);
    a.x += b4.x; a.y += b4.y; a.z += b4.z; a.w += b4.w;
    *(float4*)(out + idx) = a;
}

// ---------------- launch ----------------------------------------------------
extern "C" void kernel_launch(void* const* d_in, const int* in_sizes, int n_in,
                              void* d_out, int out_size)
{
    const float* input_seq    = (const float*)d_in[0];
    const float* memory_cells = (const float*)d_in[1];
    const float* Wk = (const float*)d_in[2];
    const float* bk = (const float*)d_in[3];
    const float* Wv = (const float*)d_in[4];
    const float* bv = (const float*)d_in[5];
    const float* Wq = (const float*)d_in[6];
    const float* bq = (const float*)d_in[7];
    const float* Wo = (const float*)d_in[8];
    const float* bo = (const float*)d_in[9];
    float* out = (float*)d_out;

    __half *p_inh, *p_memh, *p_ikh, *p_ivTh, *p_qh, *p_sch, *p_prh, *p_cch;
    __half *p_WkT, *p_WvT, *p_WqT, *p_WoT;
    float *p_mk, *p_mv, *p_sf, *p_part;
    cudaGetSymbolAddress((void**)&p_inh,  g_in_h);
    cudaGetSymbolAddress((void**)&p_memh, g_mem_h);
    cudaGetSymbolAddress((void**)&p_ikh,  g_ik_h);
    cudaGetSymbolAddress((void**)&p_ivTh, g_ivT_h);
    cudaGetSymbolAddress((void**)&p_mk,   g_mk);
    cudaGetSymbolAddress((void**)&p_mv,   g_mv);
    cudaGetSymbolAddress((void**)&p_qh,   g_q_h);
    cudaGetSymbolAddress((void**)&p_sch,  g_scores_h);
    cudaGetSymbolAddress((void**)&p_prh,  g_probs_h);
    cudaGetSymbolAddress((void**)&p_sf,   g_self);
    cudaGetSymbolAddress((void**)&p_cch,  g_concat_h);
    cudaGetSymbolAddress((void**)&p_part, g_part);
    cudaGetSymbolAddress((void**)&p_WkT,  g_WkT);
    cudaGetSymbolAddress((void**)&p_WvT,  g_WvT);
    cudaGetSymbolAddress((void**)&p_WqT,  g_WqT);
    cudaGetSymbolAddress((void**)&p_WoT,  g_WoT);

    cudaFuncSetAttribute(gemm_h<6, D_>, cudaFuncAttributeMaxDynamicSharedMemorySize, GEMM_SMEM);
    cudaFuncSetAttribute(gemm_h<2, P_>, cudaFuncAttributeMaxDynamicSharedMemorySize, GEMM_SMEM);
    cudaFuncSetAttribute(gemm_h<3, S_>, cudaFuncAttributeMaxDynamicSharedMemorySize, GEMM_SMEM);
    cudaFuncSetAttribute(gemm_h<5, 1024>, cudaFuncAttributeMaxDynamicSharedMemorySize, GEMM_SMEM);

    // fused prep (tohalf x2 + all weight transposes), one launch
    k_prep<<<13824, 256>>>(input_seq, memory_cells, Wk, Wv, Wq, Wo,
                           p_inh, p_memh, p_WkT, p_WvT, p_WqT, p_WoT);

    // all projections in one launch: mk, mv, q, ik, ivT
    gemm_h<6, D_><<<dim3(4, 416), 256, GEMM_SMEM>>>(
        p_memh, p_inh, p_WkT, p_WvT, p_WqT, bk, bv, bq,
        p_mk, p_mv, p_qh, p_ikh, p_ivTh, nullptr, nullptr);
    // scores -> fp16 (smem-staged epilogue)
    gemm_h<2, P_><<<dim3(16, 2, 64), 256, GEMM_SMEM>>>(
        p_qh, nullptr, p_ikh, nullptr, nullptr, nullptr, nullptr, nullptr,
        nullptr, nullptr, p_sch, nullptr, nullptr, nullptr, nullptr);
    // warp-per-row softmax (+fused self score)
    softmax_warp<<<(B_ * H_ * M_) / 8, 256>>>(p_sch, p_prh, p_qh, p_mk, p_sf);
    // attn @ V (+ self path) -> concat half (smem-staged epilogue)
    gemm_h<3, S_><<<dim3(4, 2, 64), 256, GEMM_SMEM>>>(
        p_prh, nullptr, p_ivTh, nullptr, nullptr, nullptr, nullptr, nullptr,
        nullptr, nullptr, p_cch, nullptr, nullptr, p_sf, p_mv);
    // output projection: split-K=4 partials + reduce
    gemm_h<5, 1024><<<dim3(4, 16, 4), 256, GEMM_SMEM>>>(
        p_cch, nullptr, p_WoT, nullptr, nullptr, nullptr, nullptr, nullptr,
        p_part, nullptr, nullptr, nullptr, nullptr, nullptr, nullptr);
    k_reduce_out<<<1024, 256>>>(p_part, bo, out);
}

// round 16
// speedup vs baseline: 1.2623x; 1.0055x over previous
#include <cuda_runtime.h>
#include <cuda_fp16.h>
#include <stdint.h>
#include <stddef.h>

#define B_ 8
#define S_ 2048
#define M_ 256
#define D_ 512
#define P_ 512
#define H_ 8
#define SCALE 0.04419417382415922f   // 1/sqrt(512)

// ---------------- scratch (device globals) ----------------------------------
__device__ __half g_in_h[B_ * S_ * D_];
__device__ __half g_mem_h[B_ * M_ * D_];
__device__ __half g_ik_h[B_ * S_ * P_];
__device__ __half g_ivT_h[B_ * P_ * S_];        // transposed V
__device__ float  g_mk[B_ * M_ * P_];
__device__ float  g_mv[B_ * M_ * P_];
__device__ __half g_q_h[B_ * H_ * M_ * P_];     // [b,h,m,p]
__device__ __half g_scores_h[(size_t)B_ * H_ * M_ * S_];
__device__ __half g_probs_h[(size_t)B_ * H_ * M_ * S_];  // UNNORMALIZED exp
__device__ float  g_self[B_ * H_ * M_];          // normalized self prob
__device__ float  g_inv[B_ * H_ * M_];           // 1/rowsum
__device__ __half g_concat_h[B_ * M_ * H_ * P_];
__device__ float  g_part[4 * 2048 * 512];       // split-K partials
__device__ __half g_WkT[P_ * D_];
__device__ __half g_WvT[P_ * D_];
__device__ __half g_WqT[H_ * P_ * D_];
__device__ __half g_WoT[P_ * H_ * P_];

// ---------------- low-level helpers -----------------------------------------
__device__ __forceinline__ void cpa16(uint32_t s, const void* g) {
    asm volatile("cp.async.cg.shared.global [%0], [%1], 16;\n" ::"r"(s), "l"(g));
}
#define CPA_COMMIT() asm volatile("cp.async.commit_group;\n" ::: "memory")
#define CPA_WAIT1()  asm volatile("cp.async.wait_group 1;\n" ::: "memory")

__device__ __forceinline__ void ldsm4(uint32_t* r, uint32_t addr) {
    asm volatile("ldmatrix.sync.aligned.m8n8.x4.shared.b16 {%0,%1,%2,%3}, [%4];"
        : "=r"(r[0]), "=r"(r[1]), "=r"(r[2]), "=r"(r[3]) : "r"(addr));
}
__device__ __forceinline__ void mma16816(float* d, const uint32_t* a,
                                         uint32_t b0, uint32_t b1) {
    asm volatile(
        "mma.sync.aligned.m16n8k16.row.col.f32.f16.f16.f32 "
        "{%0,%1,%2,%3},{%4,%5,%6,%7},{%8,%9},{%0,%1,%2,%3};"
        : "+f"(d[0]), "+f"(d[1]), "+f"(d[2]), "+f"(d[3])
        : "r"(a[0]), "r"(a[1]), "r"(a[2]), "r"(a[3]), "r"(b0), "r"(b1));
}

// SMEM: BK=64, rows padded to 72 halfs (144B stride -> ldsm conflict-free).
#define ROWP 72
#define STAGE_B (128 * ROWP * 2)
#define GEMM_SMEM (6 * STAGE_B)     // 110592 bytes

// ---------------- fused prep: tohalf(input,mem) + transposes -----------------
__device__ __forceinline__ void transpose_flat(const float* in, __half* out,
                                               int K, int N, int bx, int by,
                                               int tid) {
    __shared__ float t[32][33];
    int k0 = by * 32, n0 = bx * 32;
    int x = tid & 31, y = tid >> 5;   // 32 x 8
#pragma unroll
    for (int i = 0; i < 32; i += 8)
        t[y + i][x] = in[(size_t)(k0 + y + i) * N + n0 + x];
    __syncthreads();
#pragma unroll
    for (int i = 0; i < 32; i += 8)
        out[(size_t)(n0 + y + i) * K + k0 + x] = __float2half(t[x][y + i]);
}
__global__ __launch_bounds__(256) void k_prep(
    const float* __restrict__ input_seq, const float* __restrict__ mem,
    const float* __restrict__ Wk, const float* __restrict__ Wv,
    const float* __restrict__ Wq, const float* __restrict__ Wo,
    __half* __restrict__ in_h, __half* __restrict__ mem_h,
    __half* __restrict__ WkT, __half* __restrict__ WvT,
    __half* __restrict__ WqT, __half* __restrict__ WoT)
{
    int bid = blockIdx.x, tid = threadIdx.x;
    if (bid < 8192) {                 // tohalf input_seq
        size_t i = ((size_t)bid * 256 + tid) * 4;
        float4 v = *(const float4*)(input_seq + i);
        *(__half2*)(in_h + i)     = __floats2half2_rn(v.x, v.y);
        *(__half2*)(in_h + i + 2) = __floats2half2_rn(v.z, v.w);
    } else if (bid < 9216) {          // tohalf memory_cells
        size_t i = ((size_t)(bid - 8192) * 256 + tid) * 4;
        float4 v = *(const float4*)(mem + i);
        *(__half2*)(mem_h + i)     = __floats2half2_rn(v.x, v.y);
        *(__half2*)(mem_h + i + 2) = __floats2half2_rn(v.z, v.w);
    } else if (bid < 11776) {         // Wk/Wv/Wq transposes: 16x16x10
        int t2 = bid - 9216;
        int z = t2 >> 8, rem = t2 & 255;
        int bx = rem & 15, by = rem >> 4;
        const float* in; __half* out;
        if (z == 0)      { in = Wk; out = WkT; }
        else if (z == 1) { in = Wv; out = WvT; }
        else             { in = Wq + (size_t)(z - 2) * D_ * P_;
                           out = WqT + (size_t)(z - 2) * P_ * D_; }
        transpose_flat(in, out, D_, P_, bx, by, tid);
    } else {                          // Wo transpose: 16 x 128
        int t2 = bid - 11776;
        int bx = t2 & 15, by = t2 >> 4;
        transpose_flat(Wo, WoT, H_ * P_, P_, bx, by, tid);
    }
}

// ---------------- fp16 NT GEMM: 128x128 CTA tile, BK=64, 3-stage ------------
// 256 threads, 8 warps (2x4), 64m x 32n per warp. A,B fragments via ldmatrix.
template <int MODE, int K>
__global__ __launch_bounds__(256, 2) void gemm_h(
    const __half* __restrict__ A0, const __half* __restrict__ A1,
    const __half* __restrict__ B0, const __half* __restrict__ B1,
    const __half* __restrict__ B2,
    const float* __restrict__ bias0, const float* __restrict__ bias1,
    const float* __restrict__ bias2,
    float* __restrict__ F0, float* __restrict__ F1,
    __half* __restrict__ H0, __half* __restrict__ H1, __half* __restrict__ H2,
    const float* __restrict__ selfw, const float* __restrict__ mvp,
    const float* __restrict__ invp)
{
    extern __shared__ __align__(16) char smem[];
    const uint32_t sbase = (uint32_t)__cvta_generic_to_shared(smem);
    const uint32_t sB0 = sbase + 3 * STAGE_B;

    const int tid = threadIdx.x;
    const int lane = tid & 31, wid = tid >> 5;
    const int g = lane >> 2, tg = lane & 3;
    const int wm = wid & 1, wn = wid >> 1;
    const int n0 = blockIdx.x * 128;
    const int z = blockIdx.z;
    const int lrow = (lane & 7) + ((lane >> 3) & 1) * 8;
    const int lkb = (lane >> 4) * 8;
    const int bn_local = (lane & 7) + ((lane >> 4) & 1) * 8;
    const int bk_half = ((lane >> 3) & 1) * 8;

    int m0, part = 0, zz = 0;
    if (MODE == 6) {
        int by = blockIdx.y;
        if (by < 160) { part = 0; zz = by >> 4; m0 = (by & 15) * 128; }
        else { int t = by - 160; part = 1; zz = t >> 7; m0 = (t & 127) * 128; }
    } else {
        m0 = blockIdx.y * 128;
    }

    const __half *Ag, *Bg;
    int lda, ldb;
    if (MODE == 6) {
        lda = D_; ldb = D_;
        const __half* Bb;
        if (part == 0) {
            Ag = A0 + (size_t)m0 * lda;
            Bb = (zz == 0) ? B0 : (zz == 1) ? B1 : (B2 + (size_t)(zz - 2) * P_ * D_);
        } else {
            Ag = A1 + (size_t)m0 * lda;
            Bb = (zz == 0) ? B0 : B1;
        }
        Bg = Bb + (size_t)n0 * ldb;
    } else if (MODE == 2) {
        lda = P_; ldb = P_;
        Ag = A0 + (size_t)z * M_ * P_ + (size_t)m0 * lda;
        Bg = B0 + (size_t)(z >> 3) * S_ * P_ + (size_t)n0 * ldb;
    } else if (MODE == 3) {
        lda = S_; ldb = S_;
        Ag = A0 + (size_t)z * M_ * S_ + (size_t)m0 * lda;
        Bg = B0 + (size_t)(z >> 3) * P_ * S_ + (size_t)n0 * ldb;
    } else {  // MODE 5
        lda = H_ * P_; ldb = H_ * P_;
        Ag = A0 + (size_t)m0 * lda + z * 1024;
        Bg = B0 + (size_t)n0 * ldb + z * 1024;
    }

    const int lrw = tid >> 1, hp = tid & 1;
    const __half* gA0 = Ag + (size_t)lrw * lda + hp * 32;
    const __half* gB0 = Bg + (size_t)lrw * ldb + hp * 32;
    const uint32_t dA0 = sbase + (lrw * ROWP + hp * 32) * 2;
    const uint32_t dB0 = sB0 + (lrw * ROWP + hp * 32) * 2;

#define FILL(j) do { \
        int _s = (j) % 3; \
        const __half* _ga = gA0 + (j) * 64; \
        const __half* _gb = gB0 + (j) * 64; \
        uint32_t _da = dA0 + _s * STAGE_B; \
        uint32_t _db = dB0 + _s * STAGE_B; \
        cpa16(_da, _ga);           cpa16(_da + 16, _ga + 8); \
        cpa16(_da + 32, _ga + 16); cpa16(_da + 48, _ga + 24); \
        cpa16(_db, _gb);           cpa16(_db + 16, _gb + 8); \
        cpa16(_db + 32, _gb + 16); cpa16(_db + 48, _gb + 24); \
    } while (0)

    float acc[4][4][4] = {};
    constexpr int NK = K / 64;
    FILL(0); CPA_COMMIT();
    if (NK > 1) { FILL(1); } CPA_COMMIT();
    for (int i = 0; i < NK; i++) {
        CPA_WAIT1();
        __syncthreads();
        if (i + 2 < NK) FILL(i + 2);
        CPA_COMMIT();
        const int s = i % 3;
        const uint32_t aS = sbase + s * STAGE_B;
        const uint32_t bS = sB0 + s * STAGE_B;
#pragma unroll
        for (int kk = 0; kk < 4; kk++) {
            uint32_t a[4][4];
#pragma unroll
            for (int mt = 0; mt < 4; mt++)
                ldsm4(a[mt], aS +
                    ((wm * 64 + mt * 16 + lrow) * ROWP + kk * 16 + lkb) * 2);
#pragma unroll
            for (int np = 0; np < 2; np++) {
                uint32_t br[4];
                ldsm4(br, bS +
                    ((wn * 32 + np * 16 + bn_local) * ROWP + kk * 16 + bk_half) * 2);
#pragma unroll
                for (int mt = 0; mt < 4; mt++) {
                    mma16816(acc[mt][2 * np],     a[mt], br[0], br[1]);
                    mma16816(acc[mt][2 * np + 1], a[mt], br[2], br[3]);
                }
            }
        }
    }
#undef FILL

    // ---- ivT path: SMEM-staged transpose, coalesced stores ----
    if (MODE == 6 && part == 1 && zz == 1) {
        __syncthreads();
        __half* tb = (__half*)smem;           // [128 p][136 s-pad]
#pragma unroll
        for (int mt = 0; mt < 4; mt++)
#pragma unroll
            for (int nt = 0; nt < 4; nt++) {
                int p_l = wn * 32 + nt * 8 + 2 * tg;
                float2 bi = *(const float2*)(bias1 + n0 + p_l);
#pragma unroll
                for (int rr = 0; rr < 2; rr++) {
                    int s_l = wm * 64 + mt * 16 + g + rr * 8;
                    tb[(p_l)     * 136 + s_l] = __float2half(acc[mt][nt][2 * rr] + bi.x);
                    tb[(p_l + 1) * 136 + s_l] = __float2half(acc[mt][nt][2 * rr + 1] + bi.y);
                }
            }
        __syncthreads();
        int b = m0 >> 11, s0 = m0 & 2047;
#pragma unroll
        for (int i = 0; i < 8; i++) {
            int c = i * 256 + tid;
            int p = c >> 4, off = (c & 15) * 8;
            *(float4*)&H2[((size_t)b * P_ + n0 + p) * S_ + s0 + off] =
                *(float4*)&tb[p * 136 + off];
        }
        return;
    }

    // ---- scores path: SMEM-staged, coalesced stores ----
    if (MODE == 2) {
        __syncthreads();
        __half* tb = (__half*)smem;           // [128 m][136 s-pad]
#pragma unroll
        for (int mt = 0; mt < 4; mt++)
#pragma unroll
            for (int nt = 0; nt < 4; nt++) {
                int c_l = wn * 32 + nt * 8 + 2 * tg;
#pragma unroll
                for (int rr = 0; rr < 2; rr++) {
                    int r_l = wm * 64 + mt * 16 + g + rr * 8;
                    *(__half2*)&tb[r_l * 136 + c_l] =
                        __floats2half2_rn(acc[mt][nt][2 * rr] * SCALE,
                                          acc[mt][nt][2 * rr + 1] * SCALE);
                }
            }
        __syncthreads();
#pragma unroll
        for (int i = 0; i < 8; i++) {
            int c = i * 256 + tid;
            int r = c >> 4, off = (c & 15) * 8;
            *(float4*)&H0[((size_t)z * M_ + m0 + r) * S_ + n0 + off] =
                *(float4*)&tb[r * 136 + off];
        }
        return;
    }

    // ---- val path: SMEM-staged (acc*inv + self*mv), coalesced stores ----
    if (MODE == 3) {
        __syncthreads();
        __half* tb = (__half*)smem;           // [128 m][136 p-pad]
        int b = z >> 3, h = z & 7;
#pragma unroll
        for (int mt = 0; mt < 4; mt++)
#pragma unroll
            for (int nt = 0; nt < 4; nt++) {
                int c_l = wn * 32 + nt * 8 + 2 * tg;
#pragma unroll
                for (int rr = 0; rr < 2; rr++) {
                    int r_l = wm * 64 + mt * 16 + g + rr * 8;
                    int R = m0 + r_l;
                    float iv = invp[(size_t)z * M_ + R];
                    float sw = selfw[(size_t)z * M_ + R];
                    float2 mvv = *(const float2*)(mvp +
                        ((size_t)(b * M_ + R)) * P_ + n0 + c_l);
                    *(__half2*)&tb[r_l * 136 + c_l] =
                        __floats2half2_rn(acc[mt][nt][2 * rr] * iv + sw * mvv.x,
                                          acc[mt][nt][2 * rr + 1] * iv + sw * mvv.y);
                }
            }
        __syncthreads();
#pragma unroll
        for (int i = 0; i < 8; i++) {
            int c = i * 256 + tid;
            int r = c >> 4, off = (c & 15) * 8;
            *(float4*)&H0[(size_t)(b * M_ + m0 + r) * (H_ * P_) + h * P_ + n0 + off] =
                *(float4*)&tb[r * 136 + off];
        }
        return;
    }

#pragma unroll
    for (int mt = 0; mt < 4; mt++)
#pragma unroll
        for (int nt = 0; nt < 4; nt++) {
            int col = n0 + wn * 32 + nt * 8 + 2 * tg;
#pragma unroll
            for (int rr = 0; rr < 2; rr++) {
                int R = m0 + wm * 64 + mt * 16 + g + rr * 8;
                float v0 = acc[mt][nt][2 * rr + 0];
                float v1 = acc[mt][nt][2 * rr + 1];
                if (MODE == 6) {
                    if (part == 0) {
                        if (zz == 0) {
                            float2 bi = *(const float2*)(bias0 + col);
                            *(float2*)&F0[(size_t)R * P_ + col] =
                                make_float2(v0 + bi.x, v1 + bi.y);
                        } else if (zz == 1) {
                            float2 bi = *(const float2*)(bias1 + col);
                            *(float2*)&F1[(size_t)R * P_ + col] =
                                make_float2(v0 + bi.x, v1 + bi.y);
                        } else {
                            int h = zz - 2;
                            float2 bi = *(const float2*)(bias2 + h * P_ + col);
                            int b = R >> 8, m = R & 255;
                            *(__half2*)&H0[(((size_t)(b * H_ + h)) * M_ + m) * P_ + col] =
                                __floats2half2_rn(v0 + bi.x, v1 + bi.y);
                        }
                    } else {  // part==1, zz==0: ik
                        float2 bi = *(const float2*)(bias0 + col);
                        *(__half2*)&H1[(size_t)R * P_ + col] =
                            __floats2half2_rn(v0 + bi.x, v1 + bi.y);
                    }
                } else {  // MODE 5: split-K partial
                    *(float2*)&F0[(size_t)z * (2048 * 512) + (size_t)R * P_ + col] =
                        make_float2(v0, v1);
                }
            }
        }
}

// ---------------- streaming softmax (no-max; unnormalized exp out) ----------
// 256 threads = 8 warps; warp w owns row blockIdx.x*8+w. Single pass:
// load -> exp -> store (unnormalized) -> accumulate sum. inv folded into val GEMM.
__global__ __launch_bounds__(256) void softmax_stream(
    const __half* __restrict__ scores, __half* __restrict__ probs,
    const __half* __restrict__ q, const float* __restrict__ mk,
    float* __restrict__ selfv, float* __restrict__ invv)
{
    const int wid = threadIdx.x >> 5, lane = threadIdx.x & 31;
    const int row = blockIdx.x * 8 + wid;       // z*M + m
    const int z = row >> 8, m = row & 255, b = z >> 3;

    // ---- self score: dot(q[row], mk[b,m]) * SCALE, warp-reduced ----
    float sd = 0.f;
    {
        const float4* q4 = (const float4*)(q + (size_t)row * P_);      // 64 f4
        const float4* k4 = (const float4*)(mk + ((size_t)(b * M_ + m)) * P_);
#pragma unroll
        for (int j = 0; j < 2; j++) {
            int idx = lane + j * 32;
            float4 qf = q4[idx];
            const __half2* qh = (const __half2*)&qf;
            float4 ka = k4[2 * idx], kb = k4[2 * idx + 1];
            sd += __low2float(qh[0]) * ka.x + __high2float(qh[0]) * ka.y
                + __low2float(qh[1]) * ka.z + __high2float(qh[1]) * ka.w
                + __low2float(qh[2]) * kb.x + __high2float(qh[2]) * kb.y
                + __low2float(qh[3]) * kb.z + __high2float(qh[3]) * kb.w;
        }
        for (int o = 16; o; o >>= 1) sd += __shfl_xor_sync(0xffffffffu, sd, o);
        sd *= SCALE;
    }

    // ---- stream: exp + store unnormalized + accumulate sum ----
    const float4* sp4 = (const float4*)(scores + (size_t)row * S_);    // 256 f4
    float4* pp4 = (float4*)(probs + (size_t)row * S_);
    float s = 0.f;
#pragma unroll
    for (int j = 0; j < 8; j++) {
        float4 raw = sp4[lane + j * 32];
        const __half2* h2 = (const __half2*)&raw;
        float4 outp;
        __half2* o2 = (__half2*)&outp;
#pragma unroll
        for (int i = 0; i < 4; i++) {
            float e0 = __expf(__low2float(h2[i]));
            float e1 = __expf(__high2float(h2[i]));
            s += e0 + e1;
            o2[i] = __floats2half2_rn(e0, e1);
        }
        pp4[lane + j * 32] = outp;
    }
    float es = __expf(sd);
    if (lane == 0) s += es;
    for (int o = 16; o; o >>= 1) s += __shfl_xor_sync(0xffffffffu, s, o);
    float inv = 1.0f / s;
    if (lane == 0) {
        selfv[row] = es * inv;
        invv[row] = inv;
    }
}

// ---------------- split-K reduction + bias -----------------------------------
__global__ __launch_bounds__(256) void k_reduce_out(
    const float* __restrict__ part, const float* __restrict__ bo,
    float* __restrict__ out)
{
    int idx = (blockIdx.x * 256 + threadIdx.x) * 4;
    float4 a = *(const float4*)(part + idx);
#pragma unroll
    for (int s = 1; s < 4; s++) {
        const float4 p = *(const float4*)(part + (size_t)s * (2048 * 512) + idx);
        a.x += p.x; a.y += p.y; a.z += p.z; a.w += p.w;
    }
    int col = idx & 511;
    float4 b4 = *(const float4*)(bo + col);
    a.x += b4.x; a.y += b4.y; a.z += b4.z; a.w += b4.w;
    *(float4*)(out + idx) = a;
}

// ---------------- launch ----------------------------------------------------
extern "C" void kernel_launch(void* const* d_in, const int* in_sizes, int n_in,
                              void* d_out, int out_size)
{
    const float* input_seq    = (const float*)d_in[0];
    const float* memory_cells = (const float*)d_in[1];
    const float* Wk = (const float*)d_in[2];
    const float* bk = (const float*)d_in[3];
    const float* Wv = (const float*)d_in[4];
    const float* bv = (const float*)d_in[5];
    const float* Wq = (const float*)d_in[6];
    const float* bq = (const float*)d_in[7];
    const float* Wo = (const float*)d_in[8];
    const float* bo = (const float*)d_in[9];
    float* out = (float*)d_out;

    __half *p_inh, *p_memh, *p_ikh, *p_ivTh, *p_qh, *p_sch, *p_prh, *p_cch;
    __half *p_WkT, *p_WvT, *p_WqT, *p_WoT;
    float *p_mk, *p_mv, *p_sf, *p_iv, *p_part;
    cudaGetSymbolAddress((void**)&p_inh,  g_in_h);
    cudaGetSymbolAddress((void**)&p_memh, g_mem_h);
    cudaGetSymbolAddress((void**)&p_ikh,  g_ik_h);
    cudaGetSymbolAddress((void**)&p_ivTh, g_ivT_h);
    cudaGetSymbolAddress((void**)&p_mk,   g_mk);
    cudaGetSymbolAddress((void**)&p_mv,   g_mv);
    cudaGetSymbolAddress((void**)&p_qh,   g_q_h);
    cudaGetSymbolAddress((void**)&p_sch,  g_scores_h);
    cudaGetSymbolAddress((void**)&p_prh,  g_probs_h);
    cudaGetSymbolAddress((void**)&p_sf,   g_self);
    cudaGetSymbolAddress((void**)&p_iv,   g_inv);
    cudaGetSymbolAddress((void**)&p_cch,  g_concat_h);
    cudaGetSymbolAddress((void**)&p_part, g_part);
    cudaGetSymbolAddress((void**)&p_WkT,  g_WkT);
    cudaGetSymbolAddress((void**)&p_WvT,  g_WvT);
    cudaGetSymbolAddress((void**)&p_WqT,  g_WqT);
    cudaGetSymbolAddress((void**)&p_WoT,  g_WoT);

    cudaFuncSetAttribute(gemm_h<6, D_>, cudaFuncAttributeMaxDynamicSharedMemorySize, GEMM_SMEM);
    cudaFuncSetAttribute(gemm_h<2, P_>, cudaFuncAttributeMaxDynamicSharedMemorySize, GEMM_SMEM);
    cudaFuncSetAttribute(gemm_h<3, S_>, cudaFuncAttributeMaxDynamicSharedMemorySize, GEMM_SMEM);
    cudaFuncSetAttribute(gemm_h<5, 1024>, cudaFuncAttributeMaxDynamicSharedMemorySize, GEMM_SMEM);

    // fused prep (tohalf x2 + all weight transposes), one launch
    k_prep<<<13824, 256>>>(input_seq, memory_cells, Wk, Wv, Wq, Wo,
                           p_inh, p_memh, p_WkT, p_WvT, p_WqT, p_WoT);

    // all projections in one launch: mk, mv, q, ik, ivT
    gemm_h<6, D_><<<dim3(4, 416), 256, GEMM_SMEM>>>(
        p_memh, p_inh, p_WkT, p_WvT, p_WqT, bk, bv, bq,
        p_mk, p_mv, p_qh, p_ikh, p_ivTh, nullptr, nullptr, nullptr);
    // scores -> fp16 (smem-staged epilogue)
    gemm_h<2, P_><<<dim3(16, 2, 64), 256, GEMM_SMEM>>>(
        p_qh, nullptr, p_ikh, nullptr, nullptr, nullptr, nullptr, nullptr,
        nullptr, nullptr, p_sch, nullptr, nullptr, nullptr, nullptr, nullptr);
    // streaming softmax (+fused self score), unnormalized probs out
    softmax_stream<<<(B_ * H_ * M_) / 8, 256>>>(p_sch, p_prh, p_qh, p_mk,
                                                p_sf, p_iv);
    // attn @ V (+ self path, *inv) -> concat half (smem-staged epilogue)
    gemm_h<3, S_><<<dim3(4, 2, 64), 256, GEMM_SMEM>>>(
        p_prh, nullptr, p_ivTh, nullptr, nullptr, nullptr, nullptr, nullptr,
        nullptr, nullptr, p_cch, nullptr, nullptr, p_sf, p_mv, p_iv);
    // output projection: split-K=4 partials + reduce
    gemm_h<5, 1024><<<dim3(4, 16, 4), 256, GEMM_SMEM>>>(
        p_cch, nullptr, p_WoT, nullptr, nullptr, nullptr, nullptr, nullptr,
        p_part, nullptr, nullptr, nullptr, nullptr, nullptr, nullptr, nullptr);
    k_reduce_out<<<1024, 256>>>(p_part, bo, out);
}